// round 6
// baseline (speedup 1.0000x reference)
#include <cuda_runtime.h>
#include <float.h>
#include <cstdint>
#include <mma.h>
using namespace nvcuda;

#define BB 4
#define NN 4096
#define DIMD 512
#define HH 8
#define DH 64
#define MM 256
#define LL 16
#define BH (BB*HH)          // 32

// ------------------- scratch (device globals; no allocs) -------------------
__device__ float g_q[BH*NN*DH];
__device__ float g_k[BH*NN*DH];
__device__ float g_v[BH*NN*DH];
__device__ float g_ql[BH*MM*DH];
__device__ float g_kl[BH*MM*DH];
__device__ float g_attn2[BH*MM*MM];
__device__ float g_zA[BH*MM*MM];
__device__ float g_zB[BH*MM*MM];
__device__ float g_xz[BH*MM*MM];
__device__ float g_t[BH*MM*MM];
__device__ float g_u[BH*MM*MM];
__device__ float g_tmp1[BH*MM*DH];
__device__ float g_tmp2[BH*MM*DH];
__device__ float g_outh[BH*NN*DH];
__device__ int   g_red[2];

// strides (floats) inside dynamic smem
#define AST 40      // A tile stride: [128][40]
#define BST 136     // B tile stride: [32][136]
#define SST 136     // staging stride: [128][136]
#define B64ST 72    // B tile stride for N=64 kernels

#define CVT_FRAG(f) do { for (int _t = 0; _t < (f).num_elements; _t++) (f).x[_t] = wmma::__float_to_tf32((f).x[_t]); } while (0)

// 3xTF32 split: hi = tf32(a), lo = tf32(a - hi)
template <typename Frag>
__device__ __forceinline__ void split_frag(Frag& hi, Frag& lo, const Frag& src) {
#pragma unroll
    for (int t = 0; t < src.num_elements; t++) {
        float h = wmma::__float_to_tf32(src.x[t]);
        hi.x[t] = h;
        lo.x[t] = wmma::__float_to_tf32(src.x[t] - h);
    }
}

// ================== mma kernel 1: qkv = X @ Wqkv, scatter ==================
__global__ void k_qkv_mma(const float* __restrict__ X, const float* __restrict__ W,
                          float* __restrict__ q, float* __restrict__ k, float* __restrict__ v)
{
    extern __shared__ float smf[];
    float* As = smf;
    float* Bs = As + 128 * AST;
    float* St = Bs + 32 * BST;
    int tid = threadIdx.x, wid = tid >> 5;
    int wm = wid >> 2, wn = wid & 3;               // 2x4 warps
    int row0 = blockIdx.y * 128, col0 = blockIdx.x * 128;

    wmma::fragment<wmma::accumulator, 16, 16, 8, float> acc[4][2];
#pragma unroll
    for (int mf = 0; mf < 4; mf++)
#pragma unroll
        for (int nf = 0; nf < 2; nf++) wmma::fill_fragment(acc[mf][nf], 0.f);

    for (int k0 = 0; k0 < 512; k0 += 32) {
        for (int i = tid; i < 1024; i += 256) {
            int r = i >> 3, f = i & 7;
            *(float4*)&As[r * AST + f * 4] = *(const float4*)&X[(size_t)(row0 + r) * 512 + k0 + f * 4];
        }
        for (int i = tid; i < 1024; i += 256) {
            int kk = i >> 5, c4 = i & 31;
            *(float4*)&Bs[kk * BST + c4 * 4] = *(const float4*)&W[(size_t)(k0 + kk) * 1536 + col0 + c4 * 4];
        }
        __syncthreads();
#pragma unroll
        for (int ks = 0; ks < 4; ks++) {
            wmma::fragment<wmma::matrix_b, 16, 16, 8, wmma::precision::tf32, wmma::row_major> bf[2];
#pragma unroll
            for (int nf = 0; nf < 2; nf++) {
                wmma::load_matrix_sync(bf[nf], Bs + (ks * 8) * BST + wn * 32 + nf * 16, BST);
                CVT_FRAG(bf[nf]);
            }
#pragma unroll
            for (int mf = 0; mf < 4; mf++) {
                wmma::fragment<wmma::matrix_a, 16, 16, 8, wmma::precision::tf32, wmma::row_major> af;
                wmma::load_matrix_sync(af, As + (wm * 64 + mf * 16) * AST + ks * 8, AST);
                CVT_FRAG(af);
#pragma unroll
                for (int nf = 0; nf < 2; nf++) wmma::mma_sync(acc[mf][nf], af, bf[nf], acc[mf][nf]);
            }
        }
        __syncthreads();
    }
#pragma unroll
    for (int mf = 0; mf < 4; mf++)
#pragma unroll
        for (int nf = 0; nf < 2; nf++)
            wmma::store_matrix_sync(St + (wm * 64 + mf * 16) * SST + wn * 32 + nf * 16,
                                    acc[mf][nf], SST, wmma::mem_row_major);
    __syncthreads();
    for (int i = tid; i < 128 * 32; i += 256) {
        int r = i >> 5, c = (i & 31) * 4;
        float4 val = *(float4*)&St[r * SST + c];
        int rg = row0 + r, b = rg >> 12, n = rg & 4095;
        int cg = col0 + c, which = cg >> 9, h = (cg & 511) >> 6, d = cg & 63;
        float* dst;
        if (which == 0) { val.x *= 0.125f; val.y *= 0.125f; val.z *= 0.125f; val.w *= 0.125f; dst = q; }
        else if (which == 1) dst = k;
        else dst = v;
        *(float4*)&dst[((size_t)(b * 8 + h) * 4096 + n) * 64 + d] = val;
    }
}

// ======== mma kernel 2: batched 256^3  C = scale*(coef*A + sgn*A@B) ========
__global__ void k_g256_mma(const float* __restrict__ A, const float* __restrict__ B,
                           float* __restrict__ C, float coef, float sgn, float scale)
{
    extern __shared__ float smf[];
    float* As = smf;
    float* Bs = As + 128 * AST;
    float* St = Bs + 32 * BST;
    int tid = threadIdx.x, wid = tid >> 5;
    int wm = wid >> 2, wn = wid & 3;
    size_t base = (size_t)blockIdx.z << 16;
    int row0 = blockIdx.y * 128, col0 = blockIdx.x * 128;

    wmma::fragment<wmma::accumulator, 16, 16, 8, float> acc[4][2];
#pragma unroll
    for (int mf = 0; mf < 4; mf++)
#pragma unroll
        for (int nf = 0; nf < 2; nf++) wmma::fill_fragment(acc[mf][nf], 0.f);

    for (int k0 = 0; k0 < 256; k0 += 32) {
        for (int i = tid; i < 1024; i += 256) {
            int r = i >> 3, f = i & 7;
            *(float4*)&As[r * AST + f * 4] = *(const float4*)&A[base + (size_t)(row0 + r) * 256 + k0 + f * 4];
        }
        for (int i = tid; i < 1024; i += 256) {
            int kk = i >> 5, c4 = i & 31;
            *(float4*)&Bs[kk * BST + c4 * 4] = *(const float4*)&B[base + (size_t)(k0 + kk) * 256 + col0 + c4 * 4];
        }
        __syncthreads();
#pragma unroll
        for (int ks = 0; ks < 4; ks++) {
            wmma::fragment<wmma::matrix_b, 16, 16, 8, wmma::precision::tf32, wmma::row_major> bf[2];
#pragma unroll
            for (int nf = 0; nf < 2; nf++) {
                wmma::load_matrix_sync(bf[nf], Bs + (ks * 8) * BST + wn * 32 + nf * 16, BST);
                CVT_FRAG(bf[nf]);
            }
#pragma unroll
            for (int mf = 0; mf < 4; mf++) {
                wmma::fragment<wmma::matrix_a, 16, 16, 8, wmma::precision::tf32, wmma::row_major> af;
                wmma::load_matrix_sync(af, As + (wm * 64 + mf * 16) * AST + ks * 8, AST);
                CVT_FRAG(af);
#pragma unroll
                for (int nf = 0; nf < 2; nf++) wmma::mma_sync(acc[mf][nf], af, bf[nf], acc[mf][nf]);
            }
        }
        __syncthreads();
    }
#pragma unroll
    for (int mf = 0; mf < 4; mf++)
#pragma unroll
        for (int nf = 0; nf < 2; nf++)
            wmma::store_matrix_sync(St + (wm * 64 + mf * 16) * SST + wn * 32 + nf * 16,
                                    acc[mf][nf], SST, wmma::mem_row_major);
    __syncthreads();
    for (int i = tid; i < 128 * 32; i += 256) {
        int r = i >> 5, c = (i & 31) * 4;
        float4 sv = *(float4*)&St[r * SST + c];
        size_t go = base + (size_t)(row0 + r) * 256 + col0 + c;
        float4 av = *(const float4*)&A[go];
        float4 st;
        st.x = scale * (sgn * sv.x + coef * av.x);
        st.y = scale * (sgn * sv.y + coef * av.y);
        st.z = scale * (sgn * sv.z + coef * av.z);
        st.w = scale * (sgn * sv.w + coef * av.w);
        *(float4*)&C[go] = st;
    }
}

// ====== mma kernel 3: batched C[rows x 64] = A[rows x K] @ B[K x 64] =======
__global__ void k_b64_mma(const float* __restrict__ A, size_t sA, int lda,
                          const float* __restrict__ B, size_t sB,
                          float* __restrict__ C, size_t sC, int K)
{
    extern __shared__ float smf[];
    float* As = smf;
    float* Bs = As + 128 * AST;
    int tid = threadIdx.x, wid = tid >> 5;
    int wm = wid >> 1, wn = wid & 1;               // 4x2 warps, warp tile 32x32
    int bh = blockIdx.y;
    int row0 = blockIdx.x * 128;
    const float* Ab = A + (size_t)bh * sA;
    const float* Bb = B + (size_t)bh * sB;
    float* Cb = C + (size_t)bh * sC;

    wmma::fragment<wmma::accumulator, 16, 16, 8, float> acc[2][2];
#pragma unroll
    for (int mf = 0; mf < 2; mf++)
#pragma unroll
        for (int nf = 0; nf < 2; nf++) wmma::fill_fragment(acc[mf][nf], 0.f);

    for (int k0 = 0; k0 < K; k0 += 32) {
        for (int i = tid; i < 1024; i += 256) {
            int r = i >> 3, f = i & 7;
            *(float4*)&As[r * AST + f * 4] = *(const float4*)&Ab[(size_t)(row0 + r) * lda + k0 + f * 4];
        }
        for (int i = tid; i < 512; i += 256) {
            int kk = i >> 4, c4 = i & 15;
            *(float4*)&Bs[kk * B64ST + c4 * 4] = *(const float4*)&Bb[(size_t)(k0 + kk) * 64 + c4 * 4];
        }
        __syncthreads();
#pragma unroll
        for (int ks = 0; ks < 4; ks++) {
            wmma::fragment<wmma::matrix_b, 16, 16, 8, wmma::precision::tf32, wmma::row_major> bf[2];
#pragma unroll
            for (int nf = 0; nf < 2; nf++) {
                wmma::load_matrix_sync(bf[nf], Bs + (ks * 8) * B64ST + wn * 32 + nf * 16, B64ST);
                CVT_FRAG(bf[nf]);
            }
#pragma unroll
            for (int mf = 0; mf < 2; mf++) {
                wmma::fragment<wmma::matrix_a, 16, 16, 8, wmma::precision::tf32, wmma::row_major> af;
                wmma::load_matrix_sync(af, As + (wm * 32 + mf * 16) * AST + ks * 8, AST);
                CVT_FRAG(af);
#pragma unroll
                for (int nf = 0; nf < 2; nf++) wmma::mma_sync(acc[mf][nf], af, bf[nf], acc[mf][nf]);
            }
        }
        __syncthreads();
    }
#pragma unroll
    for (int mf = 0; mf < 2; mf++)
#pragma unroll
        for (int nf = 0; nf < 2; nf++)
            wmma::store_matrix_sync(&Cb[(size_t)(row0 + wm * 32 + mf * 16) * 64 + wn * 32 + nf * 16],
                                    acc[mf][nf], 64, wmma::mem_row_major);
}

// ============ mma kernel 4: out = gather(outh) @ Wout (M=16384) ============
__global__ void k_final_mma(const float* __restrict__ outh, const float* __restrict__ W,
                            float* __restrict__ out)
{
    extern __shared__ float smf[];
    float* As = smf;
    float* Bs = As + 128 * AST;
    int tid = threadIdx.x, wid = tid >> 5;
    int wm = wid >> 2, wn = wid & 3;
    int row0 = blockIdx.y * 128, col0 = blockIdx.x * 128;

    wmma::fragment<wmma::accumulator, 16, 16, 8, float> acc[4][2];
#pragma unroll
    for (int mf = 0; mf < 4; mf++)
#pragma unroll
        for (int nf = 0; nf < 2; nf++) wmma::fill_fragment(acc[mf][nf], 0.f);

    for (int k0 = 0; k0 < 512; k0 += 32) {
        for (int i = tid; i < 1024; i += 256) {
            int r = i >> 3, f = i & 7;
            int rg = row0 + r;
            int b = rg >> 12, n = rg & 4095;
            int kg = k0 + f * 4;
            int h = kg >> 6, d = kg & 63;
            *(float4*)&As[r * AST + f * 4] =
                *(const float4*)&outh[((size_t)(b * 8 + h) * 4096 + n) * 64 + d];
        }
        for (int i = tid; i < 1024; i += 256) {
            int kk = i >> 5, c4 = i & 31;
            *(float4*)&Bs[kk * BST + c4 * 4] = *(const float4*)&W[(size_t)(k0 + kk) * 512 + col0 + c4 * 4];
        }
        __syncthreads();
#pragma unroll
        for (int ks = 0; ks < 4; ks++) {
            wmma::fragment<wmma::matrix_b, 16, 16, 8, wmma::precision::tf32, wmma::row_major> bf[2];
#pragma unroll
            for (int nf = 0; nf < 2; nf++) {
                wmma::load_matrix_sync(bf[nf], Bs + (ks * 8) * BST + wn * 32 + nf * 16, BST);
                CVT_FRAG(bf[nf]);
            }
#pragma unroll
            for (int mf = 0; mf < 4; mf++) {
                wmma::fragment<wmma::matrix_a, 16, 16, 8, wmma::precision::tf32, wmma::row_major> af;
                wmma::load_matrix_sync(af, As + (wm * 64 + mf * 16) * AST + ks * 8, AST);
                CVT_FRAG(af);
#pragma unroll
                for (int nf = 0; nf < 2; nf++) wmma::mma_sync(acc[mf][nf], af, bf[nf], acc[mf][nf]);
            }
        }
        __syncthreads();
    }
#pragma unroll
    for (int mf = 0; mf < 4; mf++)
#pragma unroll
        for (int nf = 0; nf < 2; nf++)
            wmma::store_matrix_sync(&out[(size_t)(row0 + wm * 64 + mf * 16) * 512 + col0 + wn * 32 + nf * 16],
                                    acc[mf][nf], 512, wmma::mem_row_major);
}

// ===== fused kernel A: outh = softmax(q@kl^T) @ tmp2 + conv(v), per 64 rows =
// QK logits use 3xTF32 (near-fp32); P@tmp2 single-pass tf32.
__global__ void k_attn1_out(const float* __restrict__ Q, const float* __restrict__ KL,
                            const float* __restrict__ T2, const float* __restrict__ V,
                            const float* __restrict__ wres, float* __restrict__ outh)
{
    extern __shared__ float smf[];
    float* qv = smf;                 // 96*72: q tile (64 x ld72), later v halo (96x64)
    float* kb = smf + 96 * 72;       // 256*72: kl (col data), later tmp2
    float* S  = kb + 256 * 72;       // 64*264: scores / later output staging (ld 72)
    __shared__ float wc[33];
    int tid = threadIdx.x, wid = tid >> 5, lane = tid & 31;
    int bh = blockIdx.y, row0 = blockIdx.x * 64;
    if (tid < 33) wc[tid] = wres[(bh & 7) * 33 + tid];

    const float* Qb = Q + ((size_t)bh * NN + row0) * 64;
    for (int i = tid; i < 64 * 16; i += 256) {
        int r = i >> 4, f = i & 15;
        *(float4*)&qv[r * 72 + f * 4] = *(const float4*)&Qb[(size_t)r * 64 + f * 4];
    }
    const float* Kb = KL + (size_t)bh * MM * 64;
    for (int i = tid; i < 256 * 16; i += 256) {
        int r = i >> 4, f = i & 15;
        *(float4*)&kb[r * 72 + f * 4] = *(const float4*)&Kb[(size_t)r * 64 + f * 4];
    }
    __syncthreads();

    // GEMM1: S(64x256) = q @ kl^T  (3xTF32; warps 2x4, warp tile 32x64)
    {
        int wm = wid >> 2, wn = wid & 3;
        wmma::fragment<wmma::accumulator, 16, 16, 8, float> a1[2][4];
#pragma unroll
        for (int mf = 0; mf < 2; mf++)
#pragma unroll
            for (int nf = 0; nf < 4; nf++) wmma::fill_fragment(a1[mf][nf], 0.f);
#pragma unroll
        for (int ks = 0; ks < 8; ks++) {
            wmma::fragment<wmma::matrix_b, 16, 16, 8, wmma::precision::tf32, wmma::col_major> bh_[4], bl_[4];
#pragma unroll
            for (int nf = 0; nf < 4; nf++) {
                wmma::fragment<wmma::matrix_b, 16, 16, 8, wmma::precision::tf32, wmma::col_major> braw;
                wmma::load_matrix_sync(braw, kb + (wn * 64 + nf * 16) * 72 + ks * 8, 72);
                split_frag(bh_[nf], bl_[nf], braw);
            }
#pragma unroll
            for (int mf = 0; mf < 2; mf++) {
                wmma::fragment<wmma::matrix_a, 16, 16, 8, wmma::precision::tf32, wmma::row_major> araw, ah, al;
                wmma::load_matrix_sync(araw, qv + (wm * 32 + mf * 16) * 72 + ks * 8, 72);
                split_frag(ah, al, araw);
#pragma unroll
                for (int nf = 0; nf < 4; nf++) {
                    wmma::mma_sync(a1[mf][nf], ah, bl_[nf], a1[mf][nf]);
                    wmma::mma_sync(a1[mf][nf], al, bh_[nf], a1[mf][nf]);
                    wmma::mma_sync(a1[mf][nf], ah, bh_[nf], a1[mf][nf]);
                }
            }
        }
#pragma unroll
        for (int mf = 0; mf < 2; mf++)
#pragma unroll
            for (int nf = 0; nf < 4; nf++)
                wmma::store_matrix_sync(S + (wm * 32 + mf * 16) * 264 + wn * 64 + nf * 16,
                                        a1[mf][nf], 264, wmma::mem_row_major);
    }
    __syncthreads();

    // softmax rows (warp wid owns rows wid*8..+7; lane group of 4 per row)
    {
        int r = wid * 8 + (lane >> 2);
        float* row = S + r * 264 + (lane & 3) * 64;
        float4 vv[16];
        float m = -FLT_MAX;
#pragma unroll
        for (int f = 0; f < 16; f++) {
            vv[f] = *(float4*)&row[f * 4];
            m = fmaxf(m, fmaxf(fmaxf(vv[f].x, vv[f].y), fmaxf(vv[f].z, vv[f].w)));
        }
        m = fmaxf(m, __shfl_xor_sync(0xffffffffu, m, 1));
        m = fmaxf(m, __shfl_xor_sync(0xffffffffu, m, 2));
        float s = 0.f;
#pragma unroll
        for (int f = 0; f < 16; f++) {
            vv[f].x = expf(vv[f].x - m); vv[f].y = expf(vv[f].y - m);
            vv[f].z = expf(vv[f].z - m); vv[f].w = expf(vv[f].w - m);
            s += vv[f].x + vv[f].y + vv[f].z + vv[f].w;
        }
        s += __shfl_xor_sync(0xffffffffu, s, 1);
        s += __shfl_xor_sync(0xffffffffu, s, 2);
        float inv = 1.f / s;
#pragma unroll
        for (int f = 0; f < 16; f++) {
            vv[f].x *= inv; vv[f].y *= inv; vv[f].z *= inv; vv[f].w *= inv;
            *(float4*)&row[f * 4] = vv[f];
        }
    }
    __syncthreads();

    // reload kb with tmp2, qv with v halo
    const float* Tb = T2 + (size_t)bh * MM * 64;
    for (int i = tid; i < 256 * 16; i += 256) {
        int r = i >> 4, f = i & 15;
        *(float4*)&kb[r * 72 + f * 4] = *(const float4*)&Tb[(size_t)r * 64 + f * 4];
    }
    for (int i = tid; i < 96 * 64; i += 256) {
        int rr = i >> 6, d = i & 63;
        int n = row0 + rr - 16;
        qv[rr * 64 + d] = (n >= 0 && n < NN) ? V[((size_t)bh * NN + n) * 64 + d] : 0.f;
    }
    __syncthreads();

    // GEMM2: O(64x64) = P(64x256) @ tmp2(256x64)  (warps 4x2, warp tile 16x32)
    int wm2 = wid >> 1, wn2 = wid & 1;
    wmma::fragment<wmma::accumulator, 16, 16, 8, float> a2[2];
#pragma unroll
    for (int nf = 0; nf < 2; nf++) wmma::fill_fragment(a2[nf], 0.f);
#pragma unroll 8
    for (int ks = 0; ks < 32; ks++) {
        wmma::fragment<wmma::matrix_a, 16, 16, 8, wmma::precision::tf32, wmma::row_major> af;
        wmma::load_matrix_sync(af, S + (wm2 * 16) * 264 + ks * 8, 264);
        CVT_FRAG(af);
#pragma unroll
        for (int nf = 0; nf < 2; nf++) {
            wmma::fragment<wmma::matrix_b, 16, 16, 8, wmma::precision::tf32, wmma::row_major> bf;
            wmma::load_matrix_sync(bf, kb + (ks * 8) * 72 + wn2 * 32 + nf * 16, 72);
            CVT_FRAG(bf);
            wmma::mma_sync(a2[nf], af, bf, a2[nf]);
        }
    }
    __syncthreads();   // all P reads done before overwriting S
#pragma unroll
    for (int nf = 0; nf < 2; nf++)
        wmma::store_matrix_sync(S + (wm2 * 16) * 72 + wn2 * 32 + nf * 16, a2[nf], 72, wmma::mem_row_major);
    __syncthreads();

    // conv residual + write
    for (int i = tid; i < 64 * 16; i += 256) {
        int r = i >> 4, c = (i & 15) * 4;
        float4 o = *(float4*)&S[r * 72 + c];
#pragma unroll 1
        for (int t = 0; t < 33; t++) {
            float w = wc[t];
            float4 vb = *(float4*)&qv[(r + t) * 64 + c];
            o.x += w * vb.x; o.y += w * vb.y; o.z += w * vb.z; o.w += w * vb.w;
        }
        *(float4*)&outh[((size_t)bh * NN + row0 + r) * 64 + c] = o;
    }
}

// ===== fused kernel B: tmp1 = softmax(ql @ k^T) @ v  (flash-style) =========
// QK logits use 3xTF32; PV accumulation fp32 FFMA.
// NOTE: block-wide sync after S stores — softmax reads rows written by OTHER warps.
__global__ void k_flash3(const float* __restrict__ QL, const float* __restrict__ K,
                         const float* __restrict__ V, float* __restrict__ tmp1)
{
    extern __shared__ float smf[];
    float* qs = smf;                 // 64*72
    float* kt = qs + 64 * 72;        // 128*72
    float* vt = kt + 128 * 72;       // 128*72
    float* S  = vt + 128 * 72;       // 64*136
    int tid = threadIdx.x, wid = tid >> 5, lane = tid & 31;
    int bh = blockIdx.y, row0 = blockIdx.x * 64;

    const float* Qb = QL + ((size_t)bh * MM + row0) * 64;
    for (int i = tid; i < 64 * 16; i += 256) {
        int r = i >> 4, f = i & 15;
        *(float4*)&qs[r * 72 + f * 4] = *(const float4*)&Qb[(size_t)r * 64 + f * 4];
    }

    int r_loc = wid * 8 + (lane >> 2);         // this lane's row (4 lanes per row)
    int c0s = (lane & 3) * 32;                 // softmax chunk (32 cols of 128)
    int c0v = (lane & 3) * 16;                 // output chunk (16 cols of 64)
    float mrow = -1e30f, lrow = 0.f;
    float o[16];
#pragma unroll
    for (int i = 0; i < 16; i++) o[i] = 0.f;

    int wm = wid >> 2, wn = wid & 3;           // S warp layout 2x4, warp tile 32x32

    for (int nt = 0; nt < 32; nt++) {
        __syncthreads();   // prev PV reads of vt done
        const float* Kb = K + ((size_t)bh * NN + nt * 128) * 64;
        const float* Vb = V + ((size_t)bh * NN + nt * 128) * 64;
        for (int i = tid; i < 128 * 16; i += 256) {
            int r = i >> 4, f = i & 15;
            *(float4*)&kt[r * 72 + f * 4] = *(const float4*)&Kb[(size_t)r * 64 + f * 4];
            *(float4*)&vt[r * 72 + f * 4] = *(const float4*)&Vb[(size_t)r * 64 + f * 4];
        }
        __syncthreads();

        // S(64x128) = ql @ k^T  (3xTF32)
        wmma::fragment<wmma::accumulator, 16, 16, 8, float> a1[2][2];
#pragma unroll
        for (int mf = 0; mf < 2; mf++)
#pragma unroll
            for (int nf = 0; nf < 2; nf++) wmma::fill_fragment(a1[mf][nf], 0.f);
#pragma unroll
        for (int ks = 0; ks < 8; ks++) {
            wmma::fragment<wmma::matrix_b, 16, 16, 8, wmma::precision::tf32, wmma::col_major> bh_[2], bl_[2];
#pragma unroll
            for (int nf = 0; nf < 2; nf++) {
                wmma::fragment<wmma::matrix_b, 16, 16, 8, wmma::precision::tf32, wmma::col_major> braw;
                wmma::load_matrix_sync(braw, kt + (wn * 32 + nf * 16) * 72 + ks * 8, 72);
                split_frag(bh_[nf], bl_[nf], braw);
            }
#pragma unroll
            for (int mf = 0; mf < 2; mf++) {
                wmma::fragment<wmma::matrix_a, 16, 16, 8, wmma::precision::tf32, wmma::row_major> araw, ah, al;
                wmma::load_matrix_sync(araw, qs + (wm * 32 + mf * 16) * 72 + ks * 8, 72);
                split_frag(ah, al, araw);
#pragma unroll
                for (int nf = 0; nf < 2; nf++) {
                    wmma::mma_sync(a1[mf][nf], ah, bl_[nf], a1[mf][nf]);
                    wmma::mma_sync(a1[mf][nf], al, bh_[nf], a1[mf][nf]);
                    wmma::mma_sync(a1[mf][nf], ah, bh_[nf], a1[mf][nf]);
                }
            }
        }
#pragma unroll
        for (int mf = 0; mf < 2; mf++)
#pragma unroll
            for (int nf = 0; nf < 2; nf++)
                wmma::store_matrix_sync(S + (wm * 32 + mf * 16) * 136 + wn * 32 + nf * 16,
                                        a1[mf][nf], 136, wmma::mem_row_major);
        __syncthreads();   // FIX: softmax below reads S rows written by OTHER warps

        // online softmax update (rows owned by this warp)
        float* srow = S + r_loc * 136 + c0s;
        float4 pv[8];
        float tm = -1e30f;
#pragma unroll
        for (int f = 0; f < 8; f++) {
            pv[f] = *(float4*)&srow[f * 4];
            tm = fmaxf(tm, fmaxf(fmaxf(pv[f].x, pv[f].y), fmaxf(pv[f].z, pv[f].w)));
        }
        tm = fmaxf(tm, __shfl_xor_sync(0xffffffffu, tm, 1));
        tm = fmaxf(tm, __shfl_xor_sync(0xffffffffu, tm, 2));
        float nm = fmaxf(mrow, tm);
        float ef = expf(mrow - nm);
        float ts = 0.f;
#pragma unroll
        for (int f = 0; f < 8; f++) {
            pv[f].x = expf(pv[f].x - nm); pv[f].y = expf(pv[f].y - nm);
            pv[f].z = expf(pv[f].z - nm); pv[f].w = expf(pv[f].w - nm);
            ts += pv[f].x + pv[f].y + pv[f].z + pv[f].w;
            *(float4*)&srow[f * 4] = pv[f];
        }
        ts += __shfl_xor_sync(0xffffffffu, ts, 1);
        ts += __shfl_xor_sync(0xffffffffu, ts, 2);
        lrow = lrow * ef + ts;
        mrow = nm;
        __syncwarp();   // row chunks written by lanes of THIS warp only

        // rescale + PV accumulate
#pragma unroll
        for (int i = 0; i < 16; i++) o[i] *= ef;
        const float* prow = S + r_loc * 136;
#pragma unroll 2
        for (int j0 = 0; j0 < 128; j0 += 4) {
            float4 p4 = *(const float4*)&prow[j0];
            const float* v0 = vt + (size_t)j0 * 72 + c0v;
#pragma unroll
            for (int cc = 0; cc < 4; cc++) {
                float4 v_a = *(const float4*)&v0[cc * 4];
                float4 v_b = *(const float4*)&v0[72 + cc * 4];
                float4 v_c = *(const float4*)&v0[144 + cc * 4];
                float4 v_d = *(const float4*)&v0[216 + cc * 4];
                o[cc*4+0] += p4.x * v_a.x + p4.y * v_b.x + p4.z * v_c.x + p4.w * v_d.x;
                o[cc*4+1] += p4.x * v_a.y + p4.y * v_b.y + p4.z * v_c.y + p4.w * v_d.y;
                o[cc*4+2] += p4.x * v_a.z + p4.y * v_b.z + p4.z * v_c.z + p4.w * v_d.z;
                o[cc*4+3] += p4.x * v_a.w + p4.y * v_b.w + p4.z * v_c.w + p4.w * v_d.w;
            }
        }
    }

    float inv = 1.f / lrow;
    float* orow = tmp1 + ((size_t)bh * MM + row0 + r_loc) * 64 + c0v;
#pragma unroll
    for (int cc = 0; cc < 4; cc++) {
        float4 st = {o[cc*4] * inv, o[cc*4+1] * inv, o[cc*4+2] * inv, o[cc*4+3] * inv};
        *(float4*)&orow[cc * 4] = st;
    }
}

// ================= fp32 kernels (landmarks, sim2, pinv prep) ===============
__global__ void k_land(const float* __restrict__ q, const float* __restrict__ k,
                       float* __restrict__ ql, float* __restrict__ kl)
{
    int idx = blockIdx.x * 256 + threadIdx.x;
    int d = idx & 63;
    int m = (idx >> 6) & 255;
    int bh = idx >> 14;
    size_t base = ((size_t)bh * NN + m * LL) * DH + d;
    float sq = 0.f, sk = 0.f;
#pragma unroll
    for (int i = 0; i < LL; i++) { sq += q[base + (size_t)i * DH]; sk += k[base + (size_t)i * DH]; }
    ql[idx] = sq * (1.f / LL);
    kl[idx] = sk * (1.f / LL);
}

__global__ void k_sim_softmax(const float* __restrict__ Q, const float* __restrict__ KL,
                              float* __restrict__ Out, int nrows)
{
    extern __shared__ float smf[];
    float* ks = smf;
    float* qs = smf + 256 * 65;
    int tid = threadIdx.x;
    int bh = blockIdx.y;
    int row0 = blockIdx.x * 64;
    const float* Qb = Q + ((size_t)bh * nrows + row0) * DH;
    const float* Kb = KL + (size_t)bh * MM * DH;
    for (int i = tid; i < 256 * 64; i += 256) { int c = i >> 6, d = i & 63; ks[c * 65 + d] = Kb[i]; }
    for (int i = tid; i < 64 * 64;  i += 256) { int r = i >> 6, d = i & 63; qs[r * 65 + d] = Qb[i]; }
    __syncthreads();
    int tx = tid & 31, ty = tid >> 5;
    int c1 = tx * 4, c2 = 128 + tx * 4;
    float acc[8][8] = {};
#pragma unroll 4
    for (int d = 0; d < 64; d++) {
        float a_[8];
#pragma unroll
        for (int i = 0; i < 8; i++) a_[i] = qs[(ty * 8 + i) * 65 + d];
        float b_[8];
#pragma unroll
        for (int j = 0; j < 4; j++) { b_[j] = ks[(c1 + j) * 65 + d]; b_[4 + j] = ks[(c2 + j) * 65 + d]; }
#pragma unroll
        for (int i = 0; i < 8; i++)
#pragma unroll
            for (int j = 0; j < 8; j++) acc[i][j] += a_[i] * b_[j];
    }
#pragma unroll
    for (int i = 0; i < 8; i++) {
        float m = acc[i][0];
#pragma unroll
        for (int j = 1; j < 8; j++) m = fmaxf(m, acc[i][j]);
        for (int o = 16; o > 0; o >>= 1) m = fmaxf(m, __shfl_xor_sync(0xffffffffu, m, o));
        float s = 0.f;
#pragma unroll
        for (int j = 0; j < 8; j++) { float e = expf(acc[i][j] - m); acc[i][j] = e; s += e; }
        for (int o = 16; o > 0; o >>= 1) s += __shfl_xor_sync(0xffffffffu, s, o);
        float inv = 1.f / s;
        float* orow = Out + ((size_t)bh * nrows + row0 + ty * 8 + i) * MM;
        float4 w1 = {acc[i][0] * inv, acc[i][1] * inv, acc[i][2] * inv, acc[i][3] * inv};
        float4 w2 = {acc[i][4] * inv, acc[i][5] * inv, acc[i][6] * inv, acc[i][7] * inv};
        *(float4*)(orow + c1) = w1;
        *(float4*)(orow + c2) = w2;
    }
}

__global__ void k_zero_red(int* red) { red[0] = 0; red[1] = 0; }

__global__ void k_pinv_prep(const float* __restrict__ X, int* red)
{
    __shared__ float s1[32], s2[32];
    int bh = blockIdx.x;
    int j = threadIdx.x;
    int wid = j >> 5, lane = j & 31;
    const float* Xb = X + (size_t)bh * MM * MM;
    float cs = 0.f, rs = 0.f;
    for (int i = 0; i < MM; i++) { cs += fabsf(Xb[j * MM + i]); rs += fabsf(Xb[i * MM + j]); }
    for (int o = 16; o > 0; o >>= 1) {
        cs = fmaxf(cs, __shfl_xor_sync(0xffffffffu, cs, o));
        rs = fmaxf(rs, __shfl_xor_sync(0xffffffffu, rs, o));
    }
    if (lane == 0) { s1[wid] = cs; s2[wid] = rs; }
    __syncthreads();
    if (wid == 0) {
        float a = (lane < 8) ? s1[lane] : 0.f;
        float b = (lane < 8) ? s2[lane] : 0.f;
        for (int o = 16; o > 0; o >>= 1) {
            a = fmaxf(a, __shfl_xor_sync(0xffffffffu, a, o));
            b = fmaxf(b, __shfl_xor_sync(0xffffffffu, b, o));
        }
        if (lane == 0) {
            atomicMax(&red[0], __float_as_int(a));
            atomicMax(&red[1], __float_as_int(b));
        }
    }
}

__global__ void k_zinit(const float* __restrict__ X, float* __restrict__ Z, const int* red)
{
    float denom = __int_as_float(red[0]) * __int_as_float(red[1]) + 1e-8f;
    int idx = blockIdx.x * 256 + threadIdx.x;
    int bh = idx >> 16;
    int rem = idx & 65535;
    int i = rem >> 8, j = rem & 255;
    Z[idx] = X[((size_t)bh << 16) + j * MM + i] / denom;
}

// --------------------------- host launcher --------------------------------
extern "C" void kernel_launch(void* const* d_in, const int* in_sizes, int n_in,
                              void* d_out, int out_size)
{
    const float *x = nullptr, *wqkv = nullptr, *wout = nullptr, *wres = nullptr;
    for (int i = 0; i < n_in; i++) {
        switch (in_sizes[i]) {
            case 8388608: x = (const float*)d_in[i]; break;
            case 786432:  wqkv = (const float*)d_in[i]; break;
            case 262144:  wout = (const float*)d_in[i]; break;
            case 264:     wres = (const float*)d_in[i]; break;
            default: break;
        }
    }

    float *pq, *pk, *pv, *pql, *pkl, *pattn2;
    float *pzA, *pzB, *pxz, *pt, *pu, *ptmp1, *ptmp2, *pouth;
    int* pred;
    cudaGetSymbolAddress((void**)&pq, g_q);
    cudaGetSymbolAddress((void**)&pk, g_k);
    cudaGetSymbolAddress((void**)&pv, g_v);
    cudaGetSymbolAddress((void**)&pql, g_ql);
    cudaGetSymbolAddress((void**)&pkl, g_kl);
    cudaGetSymbolAddress((void**)&pattn2, g_attn2);
    cudaGetSymbolAddress((void**)&pzA, g_zA);
    cudaGetSymbolAddress((void**)&pzB, g_zB);
    cudaGetSymbolAddress((void**)&pxz, g_xz);
    cudaGetSymbolAddress((void**)&pt, g_t);
    cudaGetSymbolAddress((void**)&pu, g_u);
    cudaGetSymbolAddress((void**)&ptmp1, g_tmp1);
    cudaGetSymbolAddress((void**)&ptmp2, g_tmp2);
    cudaGetSymbolAddress((void**)&pouth, g_outh);
    cudaGetSymbolAddress((void**)&pred, g_red);

    size_t shmem_sim = (size_t)(256 + 64) * 65 * sizeof(float);                     // 83200
    const int SM_BIG  = (128 * AST + 32 * BST + 128 * SST) * sizeof(float);         // 107520
    const int SM_FIN  = (128 * AST + 32 * BST) * sizeof(float);                     // 37888
    const int SM_B64  = (128 * AST + 32 * B64ST) * sizeof(float);                   // 29696
    const int SM_AOUT = (96 * 72 + 256 * 72 + 64 * 264) * sizeof(float);            // 168960
    const int SM_FLSH = (64 * 72 + 128 * 72 + 128 * 72 + 64 * 136) * sizeof(float); // 126976
    cudaFuncSetAttribute(k_sim_softmax, cudaFuncAttributeMaxDynamicSharedMemorySize, (int)shmem_sim);
    cudaFuncSetAttribute(k_qkv_mma, cudaFuncAttributeMaxDynamicSharedMemorySize, SM_BIG);
    cudaFuncSetAttribute(k_g256_mma, cudaFuncAttributeMaxDynamicSharedMemorySize, SM_BIG);
    cudaFuncSetAttribute(k_final_mma, cudaFuncAttributeMaxDynamicSharedMemorySize, SM_FIN);
    cudaFuncSetAttribute(k_b64_mma, cudaFuncAttributeMaxDynamicSharedMemorySize, SM_B64);
    cudaFuncSetAttribute(k_attn1_out, cudaFuncAttributeMaxDynamicSharedMemorySize, SM_AOUT);
    cudaFuncSetAttribute(k_flash3, cudaFuncAttributeMaxDynamicSharedMemorySize, SM_FLSH);

    // 1) qkv projection + head scatter
    k_qkv_mma<<<dim3(12, 128), 256, SM_BIG>>>(x, wqkv, pq, pk, pv);
    // 2) landmarks
    k_land<<<2048, 256>>>(pq, pk, pql, pkl);
    // 3) sim2 + softmax : [bh,256,256]  (fp32 logits)
    k_sim_softmax<<<dim3(4, BH), 256, shmem_sim>>>(pql, pkl, pattn2, MM);
    // 4) pinv init
    k_zero_red<<<1, 1>>>(pred);
    k_pinv_prep<<<BH, 256>>>(pattn2, pred);
    k_zinit<<<8192, 256>>>(pattn2, pzA, pred);
    // 5) 6 Newton-Schulz iterations on tensor cores
    float* zp = pzA;
    float* z2p = pzB;
    for (int it = 0; it < 6; it++) {
        k_g256_mma<<<dim3(2, 2, BH), 256, SM_BIG>>>(pattn2, zp, pxz, 0.f, 1.f, 1.f);
        k_g256_mma<<<dim3(2, 2, BH), 256, SM_BIG>>>(pxz, pxz, pt, 7.f, -1.f, 1.f);
        k_g256_mma<<<dim3(2, 2, BH), 256, SM_BIG>>>(pxz, pt, pu, 15.f, -1.f, 1.f);
        k_g256_mma<<<dim3(2, 2, BH), 256, SM_BIG>>>(zp, pu, z2p, 13.f, -1.f, 0.25f);
        float* sw = zp; zp = z2p; z2p = sw;
    }
    // 6) tmp1 = softmax(ql @ k^T) @ v  (flash, 3xTF32 logits, race fixed)
    k_flash3<<<dim3(4, BH), 256, SM_FLSH>>>(pql, pk, pv, ptmp1);
    // 7) tmp2 = z @ tmp1 (K = 256)
    k_b64_mma<<<dim3(2, BH), 256, SM_B64>>>(zp, (size_t)MM * MM, MM,
                                            ptmp1, (size_t)MM * DH, ptmp2, (size_t)MM * DH, MM);
    // 8) outh = softmax(q @ kl^T) @ tmp2 + conv(v)  (fused, 3xTF32 logits)
    k_attn1_out<<<dim3(64, BH), 256, SM_AOUT>>>(pq, pkl, ptmp2, pv, wres, pouth);
    // 9) out = reshape(outh) @ w_out
    k_final_mma<<<dim3(4, 128), 256, SM_FIN>>>(pouth, wout, (float*)d_out);
}

// round 8
// speedup vs baseline: 1.5649x; 1.5649x over previous
#include <cuda_runtime.h>
#include <float.h>
#include <cstdint>
#include <mma.h>
using namespace nvcuda;

#define BB 4
#define NN 4096
#define DIMD 512
#define HH 8
#define DH 64
#define MM 256
#define LL 16
#define BH (BB*HH)          // 32

// ------------------- scratch (device globals; no allocs) -------------------
__device__ float g_q[BH*NN*DH];
__device__ float g_k[BH*NN*DH];
__device__ float g_v[BH*NN*DH];
__device__ float g_ql[BH*MM*DH];
__device__ float g_kl[BH*MM*DH];
__device__ float g_attn2[BH*MM*MM];
__device__ float g_zA[BH*MM*MM];
__device__ float g_zB[BH*MM*MM];
__device__ float g_xz[BH*MM*MM];
__device__ float g_t[BH*MM*MM];
__device__ float g_u[BH*MM*MM];
__device__ float g_tmp1[BH*MM*DH];
__device__ float g_tmp2[BH*MM*DH];
__device__ float g_outh[BH*NN*DH];
__device__ int   g_red[2];

// strides (floats) inside dynamic smem
#define AST 40      // A tile stride: [128][40]
#define BST 136     // B tile stride: [32][136]
#define SST 136     // staging stride: [128][136]
#define B64ST 72    // B tile stride for N=64 kernels

#define CVT_FRAG(f) do { for (int _t = 0; _t < (f).num_elements; _t++) (f).x[_t] = wmma::__float_to_tf32((f).x[_t]); } while (0)

// 3xTF32 split: hi = tf32(a), lo = tf32(a - hi)
template <typename Frag>
__device__ __forceinline__ void split_frag(Frag& hi, Frag& lo, const Frag& src) {
#pragma unroll
    for (int t = 0; t < src.num_elements; t++) {
        float h = wmma::__float_to_tf32(src.x[t]);
        hi.x[t] = h;
        lo.x[t] = wmma::__float_to_tf32(src.x[t] - h);
    }
}

// ================== mma kernel 1: qkv = X @ Wqkv, scatter ==================
// register-prefetch double buffered
__global__ void k_qkv_mma(const float* __restrict__ X, const float* __restrict__ W,
                          float* __restrict__ q, float* __restrict__ k, float* __restrict__ v)
{
    extern __shared__ float smf[];
    float* As = smf;
    float* Bs = As + 128 * AST;
    float* St = Bs + 32 * BST;
    int tid = threadIdx.x, wid = tid >> 5;
    int wm = wid >> 2, wn = wid & 3;               // 2x4 warps
    int row0 = blockIdx.y * 128, col0 = blockIdx.x * 128;
    int ra = tid >> 3, fa = tid & 7;               // A: this thread's 4 rows via +32
    int kb_ = tid >> 5, cb = tid & 31;             // B: 4 k-rows via +8

    wmma::fragment<wmma::accumulator, 16, 16, 8, float> acc[4][2];
#pragma unroll
    for (int mf = 0; mf < 4; mf++)
#pragma unroll
        for (int nf = 0; nf < 2; nf++) wmma::fill_fragment(acc[mf][nf], 0.f);

    float4 pa[4], pb[4];
#pragma unroll
    for (int i = 0; i < 4; i++) {
        pa[i] = *(const float4*)&X[(size_t)(row0 + ra + i * 32) * 512 + fa * 4];
        pb[i] = *(const float4*)&W[(size_t)(kb_ + i * 8) * 1536 + col0 + cb * 4];
    }
    for (int ci = 0; ci < 16; ci++) {
#pragma unroll
        for (int i = 0; i < 4; i++) {
            *(float4*)&As[(ra + i * 32) * AST + fa * 4] = pa[i];
            *(float4*)&Bs[(kb_ + i * 8) * BST + cb * 4] = pb[i];
        }
        __syncthreads();
        if (ci < 15) {
            int k0 = (ci + 1) * 32;
#pragma unroll
            for (int i = 0; i < 4; i++) {
                pa[i] = *(const float4*)&X[(size_t)(row0 + ra + i * 32) * 512 + k0 + fa * 4];
                pb[i] = *(const float4*)&W[(size_t)(k0 + kb_ + i * 8) * 1536 + col0 + cb * 4];
            }
        }
#pragma unroll
        for (int ks = 0; ks < 4; ks++) {
            wmma::fragment<wmma::matrix_b, 16, 16, 8, wmma::precision::tf32, wmma::row_major> bf[2];
#pragma unroll
            for (int nf = 0; nf < 2; nf++) {
                wmma::load_matrix_sync(bf[nf], Bs + (ks * 8) * BST + wn * 32 + nf * 16, BST);
                CVT_FRAG(bf[nf]);
            }
#pragma unroll
            for (int mf = 0; mf < 4; mf++) {
                wmma::fragment<wmma::matrix_a, 16, 16, 8, wmma::precision::tf32, wmma::row_major> af;
                wmma::load_matrix_sync(af, As + (wm * 64 + mf * 16) * AST + ks * 8, AST);
                CVT_FRAG(af);
#pragma unroll
                for (int nf = 0; nf < 2; nf++) wmma::mma_sync(acc[mf][nf], af, bf[nf], acc[mf][nf]);
            }
        }
        __syncthreads();
    }
#pragma unroll
    for (int mf = 0; mf < 4; mf++)
#pragma unroll
        for (int nf = 0; nf < 2; nf++)
            wmma::store_matrix_sync(St + (wm * 64 + mf * 16) * SST + wn * 32 + nf * 16,
                                    acc[mf][nf], SST, wmma::mem_row_major);
    __syncthreads();
    for (int i = tid; i < 128 * 32; i += 256) {
        int r = i >> 5, c = (i & 31) * 4;
        float4 val = *(float4*)&St[r * SST + c];
        int rg = row0 + r, b = rg >> 12, n = rg & 4095;
        int cg = col0 + c, which = cg >> 9, h = (cg & 511) >> 6, d = cg & 63;
        float* dst;
        if (which == 0) { val.x *= 0.125f; val.y *= 0.125f; val.z *= 0.125f; val.w *= 0.125f; dst = q; }
        else if (which == 1) dst = k;
        else dst = v;
        *(float4*)&dst[((size_t)(b * 8 + h) * 4096 + n) * 64 + d] = val;
    }
}

// ======== mma kernel 2: batched 256^3  C = scale*(coef*A + sgn*A@B) ========
// register-prefetch double buffered
__global__ void k_g256_mma(const float* __restrict__ A, const float* __restrict__ B,
                           float* __restrict__ C, float coef, float sgn, float scale)
{
    extern __shared__ float smf[];
    float* As = smf;
    float* Bs = As + 128 * AST;
    float* St = Bs + 32 * BST;
    int tid = threadIdx.x, wid = tid >> 5;
    int wm = wid >> 2, wn = wid & 3;
    size_t base = (size_t)blockIdx.z << 16;
    int row0 = blockIdx.y * 128, col0 = blockIdx.x * 128;
    int ra = tid >> 3, fa = tid & 7;
    int kb_ = tid >> 5, cb = tid & 31;

    wmma::fragment<wmma::accumulator, 16, 16, 8, float> acc[4][2];
#pragma unroll
    for (int mf = 0; mf < 4; mf++)
#pragma unroll
        for (int nf = 0; nf < 2; nf++) wmma::fill_fragment(acc[mf][nf], 0.f);

    float4 pa[4], pb[4];
#pragma unroll
    for (int i = 0; i < 4; i++) {
        pa[i] = *(const float4*)&A[base + (size_t)(row0 + ra + i * 32) * 256 + fa * 4];
        pb[i] = *(const float4*)&B[base + (size_t)(kb_ + i * 8) * 256 + col0 + cb * 4];
    }
    for (int ci = 0; ci < 8; ci++) {
#pragma unroll
        for (int i = 0; i < 4; i++) {
            *(float4*)&As[(ra + i * 32) * AST + fa * 4] = pa[i];
            *(float4*)&Bs[(kb_ + i * 8) * BST + cb * 4] = pb[i];
        }
        __syncthreads();
        if (ci < 7) {
            int k0 = (ci + 1) * 32;
#pragma unroll
            for (int i = 0; i < 4; i++) {
                pa[i] = *(const float4*)&A[base + (size_t)(row0 + ra + i * 32) * 256 + k0 + fa * 4];
                pb[i] = *(const float4*)&B[base + (size_t)(k0 + kb_ + i * 8) * 256 + col0 + cb * 4];
            }
        }
#pragma unroll
        for (int ks = 0; ks < 4; ks++) {
            wmma::fragment<wmma::matrix_b, 16, 16, 8, wmma::precision::tf32, wmma::row_major> bf[2];
#pragma unroll
            for (int nf = 0; nf < 2; nf++) {
                wmma::load_matrix_sync(bf[nf], Bs + (ks * 8) * BST + wn * 32 + nf * 16, BST);
                CVT_FRAG(bf[nf]);
            }
#pragma unroll
            for (int mf = 0; mf < 4; mf++) {
                wmma::fragment<wmma::matrix_a, 16, 16, 8, wmma::precision::tf32, wmma::row_major> af;
                wmma::load_matrix_sync(af, As + (wm * 64 + mf * 16) * AST + ks * 8, AST);
                CVT_FRAG(af);
#pragma unroll
                for (int nf = 0; nf < 2; nf++) wmma::mma_sync(acc[mf][nf], af, bf[nf], acc[mf][nf]);
            }
        }
        __syncthreads();
    }
#pragma unroll
    for (int mf = 0; mf < 4; mf++)
#pragma unroll
        for (int nf = 0; nf < 2; nf++)
            wmma::store_matrix_sync(St + (wm * 64 + mf * 16) * SST + wn * 32 + nf * 16,
                                    acc[mf][nf], SST, wmma::mem_row_major);
    __syncthreads();
    for (int i = tid; i < 128 * 32; i += 256) {
        int r = i >> 5, c = (i & 31) * 4;
        float4 sv = *(float4*)&St[r * SST + c];
        size_t go = base + (size_t)(row0 + r) * 256 + col0 + c;
        float4 av = *(const float4*)&A[go];
        float4 st;
        st.x = scale * (sgn * sv.x + coef * av.x);
        st.y = scale * (sgn * sv.y + coef * av.y);
        st.z = scale * (sgn * sv.z + coef * av.z);
        st.w = scale * (sgn * sv.w + coef * av.w);
        *(float4*)&C[go] = st;
    }
}

// ====== mma kernel 3: batched C[rows x 64] = A[rows x K] @ B[K x 64] =======
// register-prefetch double buffered
__global__ void k_b64_mma(const float* __restrict__ A, size_t sA, int lda,
                          const float* __restrict__ B, size_t sB,
                          float* __restrict__ C, size_t sC, int K)
{
    extern __shared__ float smf[];
    float* As = smf;
    float* Bs = As + 128 * AST;
    int tid = threadIdx.x, wid = tid >> 5;
    int wm = wid >> 1, wn = wid & 1;               // 4x2 warps, warp tile 32x32
    int bh = blockIdx.y;
    int row0 = blockIdx.x * 128;
    const float* Ab = A + (size_t)bh * sA;
    const float* Bb = B + (size_t)bh * sB;
    float* Cb = C + (size_t)bh * sC;
    int ra = tid >> 3, fa = tid & 7;
    int kb_ = tid >> 4, cb = tid & 15;             // B: 2 k-rows via +16

    wmma::fragment<wmma::accumulator, 16, 16, 8, float> acc[2][2];
#pragma unroll
    for (int mf = 0; mf < 2; mf++)
#pragma unroll
        for (int nf = 0; nf < 2; nf++) wmma::fill_fragment(acc[mf][nf], 0.f);

    float4 pa[4], pb[2];
#pragma unroll
    for (int i = 0; i < 4; i++)
        pa[i] = *(const float4*)&Ab[(size_t)(row0 + ra + i * 32) * lda + fa * 4];
#pragma unroll
    for (int i = 0; i < 2; i++)
        pb[i] = *(const float4*)&Bb[(size_t)(kb_ + i * 16) * 64 + cb * 4];

    int NC = K / 32;
    for (int ci = 0; ci < NC; ci++) {
#pragma unroll
        for (int i = 0; i < 4; i++) *(float4*)&As[(ra + i * 32) * AST + fa * 4] = pa[i];
#pragma unroll
        for (int i = 0; i < 2; i++) *(float4*)&Bs[(kb_ + i * 16) * B64ST + cb * 4] = pb[i];
        __syncthreads();
        if (ci + 1 < NC) {
            int k0 = (ci + 1) * 32;
#pragma unroll
            for (int i = 0; i < 4; i++)
                pa[i] = *(const float4*)&Ab[(size_t)(row0 + ra + i * 32) * lda + k0 + fa * 4];
#pragma unroll
            for (int i = 0; i < 2; i++)
                pb[i] = *(const float4*)&Bb[(size_t)(k0 + kb_ + i * 16) * 64 + cb * 4];
        }
#pragma unroll
        for (int ks = 0; ks < 4; ks++) {
            wmma::fragment<wmma::matrix_b, 16, 16, 8, wmma::precision::tf32, wmma::row_major> bf[2];
#pragma unroll
            for (int nf = 0; nf < 2; nf++) {
                wmma::load_matrix_sync(bf[nf], Bs + (ks * 8) * B64ST + wn * 32 + nf * 16, B64ST);
                CVT_FRAG(bf[nf]);
            }
#pragma unroll
            for (int mf = 0; mf < 2; mf++) {
                wmma::fragment<wmma::matrix_a, 16, 16, 8, wmma::precision::tf32, wmma::row_major> af;
                wmma::load_matrix_sync(af, As + (wm * 32 + mf * 16) * AST + ks * 8, AST);
                CVT_FRAG(af);
#pragma unroll
                for (int nf = 0; nf < 2; nf++) wmma::mma_sync(acc[mf][nf], af, bf[nf], acc[mf][nf]);
            }
        }
        __syncthreads();
    }
#pragma unroll
    for (int mf = 0; mf < 2; mf++)
#pragma unroll
        for (int nf = 0; nf < 2; nf++)
            wmma::store_matrix_sync(&Cb[(size_t)(row0 + wm * 32 + mf * 16) * 64 + wn * 32 + nf * 16],
                                    acc[mf][nf], 64, wmma::mem_row_major);
}

// ============ mma kernel 4: out = gather(outh) @ Wout (M=16384) ============
// register-prefetch double buffered
__global__ void k_final_mma(const float* __restrict__ outh, const float* __restrict__ W,
                            float* __restrict__ out)
{
    extern __shared__ float smf[];
    float* As = smf;
    float* Bs = As + 128 * AST;
    int tid = threadIdx.x, wid = tid >> 5;
    int wm = wid >> 2, wn = wid & 3;
    int row0 = blockIdx.y * 128, col0 = blockIdx.x * 128;
    int ra = tid >> 3, fa = tid & 7;
    int kb_ = tid >> 5, cb = tid & 31;

    wmma::fragment<wmma::accumulator, 16, 16, 8, float> acc[4][2];
#pragma unroll
    for (int mf = 0; mf < 4; mf++)
#pragma unroll
        for (int nf = 0; nf < 2; nf++) wmma::fill_fragment(acc[mf][nf], 0.f);

    float4 pa[4], pb[4];
    {
#pragma unroll
        for (int i = 0; i < 4; i++) {
            int rg = row0 + ra + i * 32;
            int b = rg >> 12, n = rg & 4095;
            int kg = fa * 4;
            int h = kg >> 6, d = kg & 63;
            pa[i] = *(const float4*)&outh[((size_t)(b * 8 + h) * 4096 + n) * 64 + d];
            pb[i] = *(const float4*)&W[(size_t)(kb_ + i * 8) * 512 + col0 + cb * 4];
        }
    }
    for (int ci = 0; ci < 16; ci++) {
#pragma unroll
        for (int i = 0; i < 4; i++) {
            *(float4*)&As[(ra + i * 32) * AST + fa * 4] = pa[i];
            *(float4*)&Bs[(kb_ + i * 8) * BST + cb * 4] = pb[i];
        }
        __syncthreads();
        if (ci < 15) {
            int k0 = (ci + 1) * 32;
#pragma unroll
            for (int i = 0; i < 4; i++) {
                int rg = row0 + ra + i * 32;
                int b = rg >> 12, n = rg & 4095;
                int kg = k0 + fa * 4;
                int h = kg >> 6, d = kg & 63;
                pa[i] = *(const float4*)&outh[((size_t)(b * 8 + h) * 4096 + n) * 64 + d];
                pb[i] = *(const float4*)&W[(size_t)(k0 + kb_ + i * 8) * 512 + col0 + cb * 4];
            }
        }
#pragma unroll
        for (int ks = 0; ks < 4; ks++) {
            wmma::fragment<wmma::matrix_b, 16, 16, 8, wmma::precision::tf32, wmma::row_major> bf[2];
#pragma unroll
            for (int nf = 0; nf < 2; nf++) {
                wmma::load_matrix_sync(bf[nf], Bs + (ks * 8) * BST + wn * 32 + nf * 16, BST);
                CVT_FRAG(bf[nf]);
            }
#pragma unroll
            for (int mf = 0; mf < 4; mf++) {
                wmma::fragment<wmma::matrix_a, 16, 16, 8, wmma::precision::tf32, wmma::row_major> af;
                wmma::load_matrix_sync(af, As + (wm * 64 + mf * 16) * AST + ks * 8, AST);
                CVT_FRAG(af);
#pragma unroll
                for (int nf = 0; nf < 2; nf++) wmma::mma_sync(acc[mf][nf], af, bf[nf], acc[mf][nf]);
            }
        }
        __syncthreads();
    }
#pragma unroll
    for (int mf = 0; mf < 4; mf++)
#pragma unroll
        for (int nf = 0; nf < 2; nf++)
            wmma::store_matrix_sync(&out[(size_t)(row0 + wm * 64 + mf * 16) * 512 + col0 + wn * 32 + nf * 16],
                                    acc[mf][nf], 512, wmma::mem_row_major);
}

// ===== fused kernel A: outh = softmax(q@kl^T) @ tmp2 + conv(v), per 64 rows =
__global__ void k_attn1_out(const float* __restrict__ Q, const float* __restrict__ KL,
                            const float* __restrict__ T2, const float* __restrict__ V,
                            const float* __restrict__ wres, float* __restrict__ outh)
{
    extern __shared__ float smf[];
    float* qv = smf;                 // 96*72: q tile (64 x ld72), later v halo (96x64)
    float* kb = smf + 96 * 72;       // 256*72: kl (col data), later tmp2
    float* S  = kb + 256 * 72;       // 64*264: scores / later output staging (ld 72)
    __shared__ float wc[33];
    int tid = threadIdx.x, wid = tid >> 5, lane = tid & 31;
    int bh = blockIdx.y, row0 = blockIdx.x * 64;
    if (tid < 33) wc[tid] = wres[(bh & 7) * 33 + tid];

    const float* Qb = Q + ((size_t)bh * NN + row0) * 64;
    for (int i = tid; i < 64 * 16; i += 256) {
        int r = i >> 4, f = i & 15;
        *(float4*)&qv[r * 72 + f * 4] = *(const float4*)&Qb[(size_t)r * 64 + f * 4];
    }
    const float* Kb = KL + (size_t)bh * MM * 64;
    for (int i = tid; i < 256 * 16; i += 256) {
        int r = i >> 4, f = i & 15;
        *(float4*)&kb[r * 72 + f * 4] = *(const float4*)&Kb[(size_t)r * 64 + f * 4];
    }
    __syncthreads();

    // GEMM1: S(64x256) = q @ kl^T  (3xTF32; warps 2x4, warp tile 32x64)
    {
        int wm = wid >> 2, wn = wid & 3;
        wmma::fragment<wmma::accumulator, 16, 16, 8, float> a1[2][4];
#pragma unroll
        for (int mf = 0; mf < 2; mf++)
#pragma unroll
            for (int nf = 0; nf < 4; nf++) wmma::fill_fragment(a1[mf][nf], 0.f);
#pragma unroll
        for (int ks = 0; ks < 8; ks++) {
            wmma::fragment<wmma::matrix_b, 16, 16, 8, wmma::precision::tf32, wmma::col_major> bh_[4], bl_[4];
#pragma unroll
            for (int nf = 0; nf < 4; nf++) {
                wmma::fragment<wmma::matrix_b, 16, 16, 8, wmma::precision::tf32, wmma::col_major> braw;
                wmma::load_matrix_sync(braw, kb + (wn * 64 + nf * 16) * 72 + ks * 8, 72);
                split_frag(bh_[nf], bl_[nf], braw);
            }
#pragma unroll
            for (int mf = 0; mf < 2; mf++) {
                wmma::fragment<wmma::matrix_a, 16, 16, 8, wmma::precision::tf32, wmma::row_major> araw, ah, al;
                wmma::load_matrix_sync(araw, qv + (wm * 32 + mf * 16) * 72 + ks * 8, 72);
                split_frag(ah, al, araw);
#pragma unroll
                for (int nf = 0; nf < 4; nf++) {
                    wmma::mma_sync(a1[mf][nf], ah, bl_[nf], a1[mf][nf]);
                    wmma::mma_sync(a1[mf][nf], al, bh_[nf], a1[mf][nf]);
                    wmma::mma_sync(a1[mf][nf], ah, bh_[nf], a1[mf][nf]);
                }
            }
        }
#pragma unroll
        for (int mf = 0; mf < 2; mf++)
#pragma unroll
            for (int nf = 0; nf < 4; nf++)
                wmma::store_matrix_sync(S + (wm * 32 + mf * 16) * 264 + wn * 64 + nf * 16,
                                        a1[mf][nf], 264, wmma::mem_row_major);
    }
    __syncthreads();

    // softmax rows (warp wid owns rows wid*8..+7; lane group of 4 per row)
    {
        int r = wid * 8 + (lane >> 2);
        float* row = S + r * 264 + (lane & 3) * 64;
        float4 vv[16];
        float m = -FLT_MAX;
#pragma unroll
        for (int f = 0; f < 16; f++) {
            vv[f] = *(float4*)&row[f * 4];
            m = fmaxf(m, fmaxf(fmaxf(vv[f].x, vv[f].y), fmaxf(vv[f].z, vv[f].w)));
        }
        m = fmaxf(m, __shfl_xor_sync(0xffffffffu, m, 1));
        m = fmaxf(m, __shfl_xor_sync(0xffffffffu, m, 2));
        float s = 0.f;
#pragma unroll
        for (int f = 0; f < 16; f++) {
            vv[f].x = expf(vv[f].x - m); vv[f].y = expf(vv[f].y - m);
            vv[f].z = expf(vv[f].z - m); vv[f].w = expf(vv[f].w - m);
            s += vv[f].x + vv[f].y + vv[f].z + vv[f].w;
        }
        s += __shfl_xor_sync(0xffffffffu, s, 1);
        s += __shfl_xor_sync(0xffffffffu, s, 2);
        float inv = 1.f / s;
#pragma unroll
        for (int f = 0; f < 16; f++) {
            vv[f].x *= inv; vv[f].y *= inv; vv[f].z *= inv; vv[f].w *= inv;
            *(float4*)&row[f * 4] = vv[f];
        }
    }
    __syncthreads();

    // reload kb with tmp2, qv with v halo
    const float* Tb = T2 + (size_t)bh * MM * 64;
    for (int i = tid; i < 256 * 16; i += 256) {
        int r = i >> 4, f = i & 15;
        *(float4*)&kb[r * 72 + f * 4] = *(const float4*)&Tb[(size_t)r * 64 + f * 4];
    }
    for (int i = tid; i < 96 * 64; i += 256) {
        int rr = i >> 6, d = i & 63;
        int n = row0 + rr - 16;
        qv[rr * 64 + d] = (n >= 0 && n < NN) ? V[((size_t)bh * NN + n) * 64 + d] : 0.f;
    }
    __syncthreads();

    // GEMM2: O(64x64) = P(64x256) @ tmp2(256x64)  (warps 4x2, warp tile 16x32)
    int wm2 = wid >> 1, wn2 = wid & 1;
    wmma::fragment<wmma::accumulator, 16, 16, 8, float> a2[2];
#pragma unroll
    for (int nf = 0; nf < 2; nf++) wmma::fill_fragment(a2[nf], 0.f);
#pragma unroll 8
    for (int ks = 0; ks < 32; ks++) {
        wmma::fragment<wmma::matrix_a, 16, 16, 8, wmma::precision::tf32, wmma::row_major> af;
        wmma::load_matrix_sync(af, S + (wm2 * 16) * 264 + ks * 8, 264);
        CVT_FRAG(af);
#pragma unroll
        for (int nf = 0; nf < 2; nf++) {
            wmma::fragment<wmma::matrix_b, 16, 16, 8, wmma::precision::tf32, wmma::row_major> bf;
            wmma::load_matrix_sync(bf, kb + (ks * 8) * 72 + wn2 * 32 + nf * 16, 72);
            CVT_FRAG(bf);
            wmma::mma_sync(a2[nf], af, bf, a2[nf]);
        }
    }
    __syncthreads();   // all P reads done before overwriting S
#pragma unroll
    for (int nf = 0; nf < 2; nf++)
        wmma::store_matrix_sync(S + (wm2 * 16) * 72 + wn2 * 32 + nf * 16, a2[nf], 72, wmma::mem_row_major);
    __syncthreads();

    // conv residual + write
    for (int i = tid; i < 64 * 16; i += 256) {
        int r = i >> 4, c = (i & 15) * 4;
        float4 o = *(float4*)&S[r * 72 + c];
#pragma unroll 1
        for (int t = 0; t < 33; t++) {
            float w = wc[t];
            float4 vb = *(float4*)&qv[(r + t) * 64 + c];
            o.x += w * vb.x; o.y += w * vb.y; o.z += w * vb.z; o.w += w * vb.w;
        }
        *(float4*)&outh[((size_t)bh * NN + row0 + r) * 64 + c] = o;
    }
}

// ===== fused kernel B: tmp1 = softmax(ql @ k^T) @ v  (flash-style) =========
// QK logits 3xTF32; PV on tensor cores (tf32) with smem-staged rescale.
__global__ void k_flash3(const float* __restrict__ QL, const float* __restrict__ K,
                         const float* __restrict__ V, float* __restrict__ tmp1)
{
    extern __shared__ float smf[];
    float* qs = smf;                 // 64*72
    float* kt = qs + 64 * 72;        // 128*72
    float* vt = kt + 128 * 72;       // 128*72
    float* S  = vt + 128 * 72;       // 64*136
    int tid = threadIdx.x, wid = tid >> 5, lane = tid & 31;
    int bh = blockIdx.y, row0 = blockIdx.x * 64;

    const float* Qb = QL + ((size_t)bh * MM + row0) * 64;
    for (int i = tid; i < 64 * 16; i += 256) {
        int r = i >> 4, f = i & 15;
        *(float4*)&qs[r * 72 + f * 4] = *(const float4*)&Qb[(size_t)r * 64 + f * 4];
    }

    int r_loc = wid * 8 + (lane >> 2);         // this lane's row (4 lanes per row)
    int c0s = (lane & 3) * 32;                 // softmax chunk (32 cols of 128)
    int c0v = (lane & 3) * 16;                 // output chunk (16 cols of 64)
    float mrow = -1e30f, lrow = 0.f;
    float o[16];
#pragma unroll
    for (int i = 0; i < 16; i++) o[i] = 0.f;

    int wm = wid >> 2, wn = wid & 3;           // QK warp layout 2x4, warp tile 32x32
    int wm2 = wid >> 1, wn2 = wid & 1;         // PV warp layout 4x2, warp tile 16x32

    for (int nt = 0; nt < 32; nt++) {
        __syncthreads();   // prev tile's S/vt reads done
        const float* Kb = K + ((size_t)bh * NN + nt * 128) * 64;
        const float* Vb = V + ((size_t)bh * NN + nt * 128) * 64;
        for (int i = tid; i < 128 * 16; i += 256) {
            int r = i >> 4, f = i & 15;
            *(float4*)&kt[r * 72 + f * 4] = *(const float4*)&Kb[(size_t)r * 64 + f * 4];
            *(float4*)&vt[r * 72 + f * 4] = *(const float4*)&Vb[(size_t)r * 64 + f * 4];
        }
        __syncthreads();

        // S(64x128) = ql @ k^T  (3xTF32)
        wmma::fragment<wmma::accumulator, 16, 16, 8, float> a1[2][2];
#pragma unroll
        for (int mf = 0; mf < 2; mf++)
#pragma unroll
            for (int nf = 0; nf < 2; nf++) wmma::fill_fragment(a1[mf][nf], 0.f);
#pragma unroll
        for (int ks = 0; ks < 8; ks++) {
            wmma::fragment<wmma::matrix_b, 16, 16, 8, wmma::precision::tf32, wmma::col_major> bh_[2], bl_[2];
#pragma unroll
            for (int nf = 0; nf < 2; nf++) {
                wmma::fragment<wmma::matrix_b, 16, 16, 8, wmma::precision::tf32, wmma::col_major> braw;
                wmma::load_matrix_sync(braw, kt + (wn * 32 + nf * 16) * 72 + ks * 8, 72);
                split_frag(bh_[nf], bl_[nf], braw);
            }
#pragma unroll
            for (int mf = 0; mf < 2; mf++) {
                wmma::fragment<wmma::matrix_a, 16, 16, 8, wmma::precision::tf32, wmma::row_major> araw, ah, al;
                wmma::load_matrix_sync(araw, qs + (wm * 32 + mf * 16) * 72 + ks * 8, 72);
                split_frag(ah, al, araw);
#pragma unroll
                for (int nf = 0; nf < 2; nf++) {
                    wmma::mma_sync(a1[mf][nf], ah, bl_[nf], a1[mf][nf]);
                    wmma::mma_sync(a1[mf][nf], al, bh_[nf], a1[mf][nf]);
                    wmma::mma_sync(a1[mf][nf], ah, bh_[nf], a1[mf][nf]);
                }
            }
        }
#pragma unroll
        for (int mf = 0; mf < 2; mf++)
#pragma unroll
            for (int nf = 0; nf < 2; nf++)
                wmma::store_matrix_sync(S + (wm * 32 + mf * 16) * 136 + wn * 32 + nf * 16,
                                        a1[mf][nf], 136, wmma::mem_row_major);
        __syncthreads();   // softmax reads S rows written by other warps

        // online softmax update (each warp owns 8 rows; 4 lanes per row)
        float ef;
        {
            float* srow = S + r_loc * 136 + c0s;
            float4 pv[8];
            float tm = -1e30f;
#pragma unroll
            for (int f = 0; f < 8; f++) {
                pv[f] = *(float4*)&srow[f * 4];
                tm = fmaxf(tm, fmaxf(fmaxf(pv[f].x, pv[f].y), fmaxf(pv[f].z, pv[f].w)));
            }
            tm = fmaxf(tm, __shfl_xor_sync(0xffffffffu, tm, 1));
            tm = fmaxf(tm, __shfl_xor_sync(0xffffffffu, tm, 2));
            float nm = fmaxf(mrow, tm);
            ef = expf(mrow - nm);
            float ts = 0.f;
#pragma unroll
            for (int f = 0; f < 8; f++) {
                pv[f].x = expf(pv[f].x - nm); pv[f].y = expf(pv[f].y - nm);
                pv[f].z = expf(pv[f].z - nm); pv[f].w = expf(pv[f].w - nm);
                ts += pv[f].x + pv[f].y + pv[f].z + pv[f].w;
                *(float4*)&srow[f * 4] = pv[f];
            }
            ts += __shfl_xor_sync(0xffffffffu, ts, 1);
            ts += __shfl_xor_sync(0xffffffffu, ts, 2);
            lrow = lrow * ef + ts;
            mrow = nm;
        }
        __syncthreads();   // PV mma below reads all P rows

        // PV: Opart(64x64) = P(64x128) @ V(128x64) on tensor cores
        wmma::fragment<wmma::accumulator, 16, 16, 8, float> apv[2];
#pragma unroll
        for (int nf = 0; nf < 2; nf++) wmma::fill_fragment(apv[nf], 0.f);
#pragma unroll
        for (int ks = 0; ks < 16; ks++) {
            wmma::fragment<wmma::matrix_a, 16, 16, 8, wmma::precision::tf32, wmma::row_major> af;
            wmma::load_matrix_sync(af, S + (wm2 * 16) * 136 + ks * 8, 136);
            CVT_FRAG(af);
#pragma unroll
            for (int nf = 0; nf < 2; nf++) {
                wmma::fragment<wmma::matrix_b, 16, 16, 8, wmma::precision::tf32, wmma::row_major> bf;
                wmma::load_matrix_sync(bf, vt + (ks * 8) * 72 + wn2 * 32 + nf * 16, 72);
                CVT_FRAG(bf);
                wmma::mma_sync(apv[nf], af, bf, apv[nf]);
            }
        }
        __syncthreads();   // all P reads done before staging overwrites S
#pragma unroll
        for (int nf = 0; nf < 2; nf++)
            wmma::store_matrix_sync(S + (wm2 * 16) * 136 + wn2 * 32 + nf * 16,
                                    apv[nf], 136, wmma::mem_row_major);
        __syncthreads();   // staging visible to all

        // o = o*ef + Opart  (16 cols per lane)
        {
            const float* prow = S + r_loc * 136 + c0v;
#pragma unroll
            for (int cc = 0; cc < 4; cc++) {
                float4 po = *(const float4*)&prow[cc * 4];
                o[cc*4+0] = o[cc*4+0] * ef + po.x;
                o[cc*4+1] = o[cc*4+1] * ef + po.y;
                o[cc*4+2] = o[cc*4+2] * ef + po.z;
                o[cc*4+3] = o[cc*4+3] * ef + po.w;
            }
        }
    }

    float inv = 1.f / lrow;
    float* orow = tmp1 + ((size_t)bh * MM + row0 + r_loc) * 64 + c0v;
#pragma unroll
    for (int cc = 0; cc < 4; cc++) {
        float4 st = {o[cc*4] * inv, o[cc*4+1] * inv, o[cc*4+2] * inv, o[cc*4+3] * inv};
        *(float4*)&orow[cc * 4] = st;
    }
}

// ================= fp32 kernels (landmarks, sim2, pinv prep) ===============
__global__ void k_land(const float* __restrict__ q, const float* __restrict__ k,
                       float* __restrict__ ql, float* __restrict__ kl)
{
    int idx = blockIdx.x * 256 + threadIdx.x;
    int d = idx & 63;
    int m = (idx >> 6) & 255;
    int bh = idx >> 14;
    size_t base = ((size_t)bh * NN + m * LL) * DH + d;
    float sq = 0.f, sk = 0.f;
#pragma unroll
    for (int i = 0; i < LL; i++) { sq += q[base + (size_t)i * DH]; sk += k[base + (size_t)i * DH]; }
    ql[idx] = sq * (1.f / LL);
    kl[idx] = sk * (1.f / LL);
}

__global__ void k_sim_softmax(const float* __restrict__ Q, const float* __restrict__ KL,
                              float* __restrict__ Out, int nrows)
{
    extern __shared__ float smf[];
    float* ks = smf;
    float* qs = smf + 256 * 65;
    int tid = threadIdx.x;
    int bh = blockIdx.y;
    int row0 = blockIdx.x * 64;
    const float* Qb = Q + ((size_t)bh * nrows + row0) * DH;
    const float* Kb = KL + (size_t)bh * MM * DH;
    for (int i = tid; i < 256 * 64; i += 256) { int c = i >> 6, d = i & 63; ks[c * 65 + d] = Kb[i]; }
    for (int i = tid; i < 64 * 64;  i += 256) { int r = i >> 6, d = i & 63; qs[r * 65 + d] = Qb[i]; }
    __syncthreads();
    int tx = tid & 31, ty = tid >> 5;
    int c1 = tx * 4, c2 = 128 + tx * 4;
    float acc[8][8] = {};
#pragma unroll 4
    for (int d = 0; d < 64; d++) {
        float a_[8];
#pragma unroll
        for (int i = 0; i < 8; i++) a_[i] = qs[(ty * 8 + i) * 65 + d];
        float b_[8];
#pragma unroll
        for (int j = 0; j < 4; j++) { b_[j] = ks[(c1 + j) * 65 + d]; b_[4 + j] = ks[(c2 + j) * 65 + d]; }
#pragma unroll
        for (int i = 0; i < 8; i++)
#pragma unroll
            for (int j = 0; j < 8; j++) acc[i][j] += a_[i] * b_[j];
    }
#pragma unroll
    for (int i = 0; i < 8; i++) {
        float m = acc[i][0];
#pragma unroll
        for (int j = 1; j < 8; j++) m = fmaxf(m, acc[i][j]);
        for (int o = 16; o > 0; o >>= 1) m = fmaxf(m, __shfl_xor_sync(0xffffffffu, m, o));
        float s = 0.f;
#pragma unroll
        for (int j = 0; j < 8; j++) { float e = expf(acc[i][j] - m); acc[i][j] = e; s += e; }
        for (int o = 16; o > 0; o >>= 1) s += __shfl_xor_sync(0xffffffffu, s, o);
        float inv = 1.f / s;
        float* orow = Out + ((size_t)bh * nrows + row0 + ty * 8 + i) * MM;
        float4 w1 = {acc[i][0] * inv, acc[i][1] * inv, acc[i][2] * inv, acc[i][3] * inv};
        float4 w2 = {acc[i][4] * inv, acc[i][5] * inv, acc[i][6] * inv, acc[i][7] * inv};
        *(float4*)(orow + c1) = w1;
        *(float4*)(orow + c2) = w2;
    }
}

__global__ void k_pinv_prep(const float* __restrict__ X, int* red)
{
    __shared__ float s1[32], s2[32];
    int bh = blockIdx.x;
    int j = threadIdx.x;
    int wid = j >> 5, lane = j & 31;
    const float* Xb = X + (size_t)bh * MM * MM;
    float cs = 0.f, rs = 0.f;
    for (int i = 0; i < MM; i++) { cs += fabsf(Xb[j * MM + i]); rs += fabsf(Xb[i * MM + j]); }
    for (int o = 16; o > 0; o >>= 1) {
        cs = fmaxf(cs, __shfl_xor_sync(0xffffffffu, cs, o));
        rs = fmaxf(rs, __shfl_xor_sync(0xffffffffu, rs, o));
    }
    if (lane == 0) { s1[wid] = cs; s2[wid] = rs; }
    __syncthreads();
    if (wid == 0) {
        float a = (lane < 8) ? s1[lane] : 0.f;
        float b = (lane < 8) ? s2[lane] : 0.f;
        for (int o = 16; o > 0; o >>= 1) {
            a = fmaxf(a, __shfl_xor_sync(0xffffffffu, a, o));
            b = fmaxf(b, __shfl_xor_sync(0xffffffffu, b, o));
        }
        if (lane == 0) {
            atomicMax(&red[0], __float_as_int(a));
            atomicMax(&red[1], __float_as_int(b));
        }
    }
}

__global__ void k_zinit(const float* __restrict__ X, float* __restrict__ Z, const int* red)
{
    float denom = __int_as_float(red[0]) * __int_as_float(red[1]) + 1e-8f;
    int idx = blockIdx.x * 256 + threadIdx.x;
    int bh = idx >> 16;
    int rem = idx & 65535;
    int i = rem >> 8, j = rem & 255;
    Z[idx] = X[((size_t)bh << 16) + j * MM + i] / denom;
}

// --------------------------- host launcher --------------------------------
extern "C" void kernel_launch(void* const* d_in, const int* in_sizes, int n_in,
                              void* d_out, int out_size)
{
    const float *x = nullptr, *wqkv = nullptr, *wout = nullptr, *wres = nullptr;
    for (int i = 0; i < n_in; i++) {
        switch (in_sizes[i]) {
            case 8388608: x = (const float*)d_in[i]; break;
            case 786432:  wqkv = (const float*)d_in[i]; break;
            case 262144:  wout = (const float*)d_in[i]; break;
            case 264:     wres = (const float*)d_in[i]; break;
            default: break;
        }
    }

    float *pq, *pk, *pv, *pql, *pkl, *pattn2;
    float *pzA, *pzB, *pxz, *pt, *pu, *ptmp1, *ptmp2, *pouth;
    int* pred;
    cudaGetSymbolAddress((void**)&pq, g_q);
    cudaGetSymbolAddress((void**)&pk, g_k);
    cudaGetSymbolAddress((void**)&pv, g_v);
    cudaGetSymbolAddress((void**)&pql, g_ql);
    cudaGetSymbolAddress((void**)&pkl, g_kl);
    cudaGetSymbolAddress((void**)&pattn2, g_attn2);
    cudaGetSymbolAddress((void**)&pzA, g_zA);
    cudaGetSymbolAddress((void**)&pzB, g_zB);
    cudaGetSymbolAddress((void**)&pxz, g_xz);
    cudaGetSymbolAddress((void**)&pt, g_t);
    cudaGetSymbolAddress((void**)&pu, g_u);
    cudaGetSymbolAddress((void**)&ptmp1, g_tmp1);
    cudaGetSymbolAddress((void**)&ptmp2, g_tmp2);
    cudaGetSymbolAddress((void**)&pouth, g_outh);
    cudaGetSymbolAddress((void**)&pred, g_red);

    size_t shmem_sim = (size_t)(256 + 64) * 65 * sizeof(float);                     // 83200
    const int SM_BIG  = (128 * AST + 32 * BST + 128 * SST) * sizeof(float);         // 107520
    const int SM_FIN  = (128 * AST + 32 * BST) * sizeof(float);                     // 37888
    const int SM_B64  = (128 * AST + 32 * B64ST) * sizeof(float);                   // 29696
    const int SM_AOUT = (96 * 72 + 256 * 72 + 64 * 264) * sizeof(float);            // 168960
    const int SM_FLSH = (64 * 72 + 128 * 72 + 128 * 72 + 64 * 136) * sizeof(float); // 126976
    cudaFuncSetAttribute(k_sim_softmax, cudaFuncAttributeMaxDynamicSharedMemorySize, (int)shmem_sim);
    cudaFuncSetAttribute(k_qkv_mma, cudaFuncAttributeMaxDynamicSharedMemorySize, SM_BIG);
    cudaFuncSetAttribute(k_g256_mma, cudaFuncAttributeMaxDynamicSharedMemorySize, SM_BIG);
    cudaFuncSetAttribute(k_final_mma, cudaFuncAttributeMaxDynamicSharedMemorySize, SM_FIN);
    cudaFuncSetAttribute(k_b64_mma, cudaFuncAttributeMaxDynamicSharedMemorySize, SM_B64);
    cudaFuncSetAttribute(k_attn1_out, cudaFuncAttributeMaxDynamicSharedMemorySize, SM_AOUT);
    cudaFuncSetAttribute(k_flash3, cudaFuncAttributeMaxDynamicSharedMemorySize, SM_FLSH);

    // 1) qkv projection + head scatter
    k_qkv_mma<<<dim3(12, 128), 256, SM_BIG>>>(x, wqkv, pq, pk, pv);
    // 2) landmarks
    k_land<<<2048, 256>>>(pq, pk, pql, pkl);
    // 3) sim2 + softmax : [bh,256,256]  (fp32 logits)
    k_sim_softmax<<<dim3(4, BH), 256, shmem_sim>>>(pql, pkl, pattn2, MM);
    // 4) pinv init
    cudaMemsetAsync(pred, 0, 2 * sizeof(int));
    k_pinv_prep<<<BH, 256>>>(pattn2, pred);
    k_zinit<<<8192, 256>>>(pattn2, pzA, pred);
    // 5) 6 Newton-Schulz iterations on tensor cores
    float* zp = pzA;
    float* z2p = pzB;
    for (int it = 0; it < 6; it++) {
        k_g256_mma<<<dim3(2, 2, BH), 256, SM_BIG>>>(pattn2, zp, pxz, 0.f, 1.f, 1.f);
        k_g256_mma<<<dim3(2, 2, BH), 256, SM_BIG>>>(pxz, pxz, pt, 7.f, -1.f, 1.f);
        k_g256_mma<<<dim3(2, 2, BH), 256, SM_BIG>>>(pxz, pt, pu, 15.f, -1.f, 1.f);
        k_g256_mma<<<dim3(2, 2, BH), 256, SM_BIG>>>(zp, pu, z2p, 13.f, -1.f, 0.25f);
        float* sw = zp; zp = z2p; z2p = sw;
    }
    // 6) tmp1 = softmax(ql @ k^T) @ v  (flash, 3xTF32 logits, tc PV)
    k_flash3<<<dim3(4, BH), 256, SM_FLSH>>>(pql, pk, pv, ptmp1);
    // 7) tmp2 = z @ tmp1 (K = 256)
    k_b64_mma<<<dim3(2, BH), 256, SM_B64>>>(zp, (size_t)MM * MM, MM,
                                            ptmp1, (size_t)MM * DH, ptmp2, (size_t)MM * DH, MM);
    // 8) outh = softmax(q @ kl^T) @ tmp2 + conv(v)  (fused, 3xTF32 logits)
    k_attn1_out<<<dim3(64, BH), 256, SM_AOUT>>>(pq, pkl, ptmp2, pv, wres, pouth);
    // 9) out = reshape(outh) @ w_out
    k_final_mma<<<dim3(4, 128), 256, SM_FIN>>>(pouth, wout, (float*)d_out);
}

// round 11
// speedup vs baseline: 1.6381x; 1.0468x over previous
#include <cuda_runtime.h>
#include <float.h>
#include <cstdint>
#include <mma.h>
using namespace nvcuda;

#define BB 4
#define NN 4096
#define DIMD 512
#define HH 8
#define DH 64
#define MM 256
#define LL 16
#define BH (BB*HH)          // 32

// ------------------- scratch (device globals; no allocs) -------------------
__device__ float g_q[BH*NN*DH];
__device__ float g_k[BH*NN*DH];
__device__ float g_v[BH*NN*DH];
__device__ float g_ql[BH*MM*DH];
__device__ float g_kl[BH*MM*DH];
__device__ float g_attn2[BH*MM*MM];
__device__ float g_zA[BH*MM*MM];
__device__ float g_zB[BH*MM*MM];
__device__ float g_xz[BH*MM*MM];
__device__ float g_t[BH*MM*MM];
__device__ float g_u[BH*MM*MM];
__device__ float g_tmp1[BH*MM*DH];
__device__ float g_tmp2[BH*MM*DH];
__device__ float g_outh[BH*NN*DH];
__device__ int   g_red[2];

// strides (floats) inside dynamic smem
#define AST 40      // A tile stride: [128][40]
#define BST 136     // B tile stride: [32][136]
#define SST 136     // staging stride: [128][136]
#define B64ST 72    // B tile stride for N=64 kernels

#define CVT_FRAG(f) do { for (int _t = 0; _t < (f).num_elements; _t++) (f).x[_t] = wmma::__float_to_tf32((f).x[_t]); } while (0)

// 3xTF32 split: hi = tf32(a), lo = tf32(a - hi)
template <typename Frag>
__device__ __forceinline__ void split_frag(Frag& hi, Frag& lo, const Frag& src) {
#pragma unroll
    for (int t = 0; t < src.num_elements; t++) {
        float h = wmma::__float_to_tf32(src.x[t]);
        hi.x[t] = h;
        lo.x[t] = wmma::__float_to_tf32(src.x[t] - h);
    }
}

// ================== mma kernel 1: qkv = X @ Wqkv, scatter ==================
// register-prefetch double buffered
__global__ void k_qkv_mma(const float* __restrict__ X, const float* __restrict__ W,
                          float* __restrict__ q, float* __restrict__ k, float* __restrict__ v)
{
    extern __shared__ float smf[];
    float* As = smf;
    float* Bs = As + 128 * AST;
    float* St = Bs + 32 * BST;
    int tid = threadIdx.x, wid = tid >> 5;
    int wm = wid >> 2, wn = wid & 3;               // 2x4 warps
    int row0 = blockIdx.y * 128, col0 = blockIdx.x * 128;
    int ra = tid >> 3, fa = tid & 7;               // A: this thread's 4 rows via +32
    int kb_ = tid >> 5, cb = tid & 31;             // B: 4 k-rows via +8

    wmma::fragment<wmma::accumulator, 16, 16, 8, float> acc[4][2];
#pragma unroll
    for (int mf = 0; mf < 4; mf++)
#pragma unroll
        for (int nf = 0; nf < 2; nf++) wmma::fill_fragment(acc[mf][nf], 0.f);

    float4 pa[4], pb[4];
#pragma unroll
    for (int i = 0; i < 4; i++) {
        pa[i] = *(const float4*)&X[(size_t)(row0 + ra + i * 32) * 512 + fa * 4];
        pb[i] = *(const float4*)&W[(size_t)(kb_ + i * 8) * 1536 + col0 + cb * 4];
    }
    for (int ci = 0; ci < 16; ci++) {
#pragma unroll
        for (int i = 0; i < 4; i++) {
            *(float4*)&As[(ra + i * 32) * AST + fa * 4] = pa[i];
            *(float4*)&Bs[(kb_ + i * 8) * BST + cb * 4] = pb[i];
        }
        __syncthreads();
        if (ci < 15) {
            int k0 = (ci + 1) * 32;
#pragma unroll
            for (int i = 0; i < 4; i++) {
                pa[i] = *(const float4*)&X[(size_t)(row0 + ra + i * 32) * 512 + k0 + fa * 4];
                pb[i] = *(const float4*)&W[(size_t)(k0 + kb_ + i * 8) * 1536 + col0 + cb * 4];
            }
        }
#pragma unroll
        for (int ks = 0; ks < 4; ks++) {
            wmma::fragment<wmma::matrix_b, 16, 16, 8, wmma::precision::tf32, wmma::row_major> bf[2];
#pragma unroll
            for (int nf = 0; nf < 2; nf++) {
                wmma::load_matrix_sync(bf[nf], Bs + (ks * 8) * BST + wn * 32 + nf * 16, BST);
                CVT_FRAG(bf[nf]);
            }
#pragma unroll
            for (int mf = 0; mf < 4; mf++) {
                wmma::fragment<wmma::matrix_a, 16, 16, 8, wmma::precision::tf32, wmma::row_major> af;
                wmma::load_matrix_sync(af, As + (wm * 64 + mf * 16) * AST + ks * 8, AST);
                CVT_FRAG(af);
#pragma unroll
                for (int nf = 0; nf < 2; nf++) wmma::mma_sync(acc[mf][nf], af, bf[nf], acc[mf][nf]);
            }
        }
        __syncthreads();
    }
#pragma unroll
    for (int mf = 0; mf < 4; mf++)
#pragma unroll
        for (int nf = 0; nf < 2; nf++)
            wmma::store_matrix_sync(St + (wm * 64 + mf * 16) * SST + wn * 32 + nf * 16,
                                    acc[mf][nf], SST, wmma::mem_row_major);
    __syncthreads();
    for (int i = tid; i < 128 * 32; i += 256) {
        int r = i >> 5, c = (i & 31) * 4;
        float4 val = *(float4*)&St[r * SST + c];
        int rg = row0 + r, b = rg >> 12, n = rg & 4095;
        int cg = col0 + c, which = cg >> 9, h = (cg & 511) >> 6, d = cg & 63;
        float* dst;
        if (which == 0) { val.x *= 0.125f; val.y *= 0.125f; val.z *= 0.125f; val.w *= 0.125f; dst = q; }
        else if (which == 1) dst = k;
        else dst = v;
        *(float4*)&dst[((size_t)(b * 8 + h) * 4096 + n) * 64 + d] = val;
    }
}

// ======== mma kernel 2: batched 256^3  C = scale*(coef*A + sgn*A@B) ========
// register-prefetch double buffered
__global__ void k_g256_mma(const float* __restrict__ A, const float* __restrict__ B,
                           float* __restrict__ C, float coef, float sgn, float scale)
{
    extern __shared__ float smf[];
    float* As = smf;
    float* Bs = As + 128 * AST;
    float* St = Bs + 32 * BST;
    int tid = threadIdx.x, wid = tid >> 5;
    int wm = wid >> 2, wn = wid & 3;
    size_t base = (size_t)blockIdx.z << 16;
    int row0 = blockIdx.y * 128, col0 = blockIdx.x * 128;
    int ra = tid >> 3, fa = tid & 7;
    int kb_ = tid >> 5, cb = tid & 31;

    wmma::fragment<wmma::accumulator, 16, 16, 8, float> acc[4][2];
#pragma unroll
    for (int mf = 0; mf < 4; mf++)
#pragma unroll
        for (int nf = 0; nf < 2; nf++) wmma::fill_fragment(acc[mf][nf], 0.f);

    float4 pa[4], pb[4];
#pragma unroll
    for (int i = 0; i < 4; i++) {
        pa[i] = *(const float4*)&A[base + (size_t)(row0 + ra + i * 32) * 256 + fa * 4];
        pb[i] = *(const float4*)&B[base + (size_t)(kb_ + i * 8) * 256 + col0 + cb * 4];
    }
    for (int ci = 0; ci < 8; ci++) {
#pragma unroll
        for (int i = 0; i < 4; i++) {
            *(float4*)&As[(ra + i * 32) * AST + fa * 4] = pa[i];
            *(float4*)&Bs[(kb_ + i * 8) * BST + cb * 4] = pb[i];
        }
        __syncthreads();
        if (ci < 7) {
            int k0 = (ci + 1) * 32;
#pragma unroll
            for (int i = 0; i < 4; i++) {
                pa[i] = *(const float4*)&A[base + (size_t)(row0 + ra + i * 32) * 256 + k0 + fa * 4];
                pb[i] = *(const float4*)&B[base + (size_t)(k0 + kb_ + i * 8) * 256 + col0 + cb * 4];
            }
        }
#pragma unroll
        for (int ks = 0; ks < 4; ks++) {
            wmma::fragment<wmma::matrix_b, 16, 16, 8, wmma::precision::tf32, wmma::row_major> bf[2];
#pragma unroll
            for (int nf = 0; nf < 2; nf++) {
                wmma::load_matrix_sync(bf[nf], Bs + (ks * 8) * BST + wn * 32 + nf * 16, BST);
                CVT_FRAG(bf[nf]);
            }
#pragma unroll
            for (int mf = 0; mf < 4; mf++) {
                wmma::fragment<wmma::matrix_a, 16, 16, 8, wmma::precision::tf32, wmma::row_major> af;
                wmma::load_matrix_sync(af, As + (wm * 64 + mf * 16) * AST + ks * 8, AST);
                CVT_FRAG(af);
#pragma unroll
                for (int nf = 0; nf < 2; nf++) wmma::mma_sync(acc[mf][nf], af, bf[nf], acc[mf][nf]);
            }
        }
        __syncthreads();
    }
#pragma unroll
    for (int mf = 0; mf < 4; mf++)
#pragma unroll
        for (int nf = 0; nf < 2; nf++)
            wmma::store_matrix_sync(St + (wm * 64 + mf * 16) * SST + wn * 32 + nf * 16,
                                    acc[mf][nf], SST, wmma::mem_row_major);
    __syncthreads();
    for (int i = tid; i < 128 * 32; i += 256) {
        int r = i >> 5, c = (i & 31) * 4;
        float4 sv = *(float4*)&St[r * SST + c];
        size_t go = base + (size_t)(row0 + r) * 256 + col0 + c;
        float4 av = *(const float4*)&A[go];
        float4 st;
        st.x = scale * (sgn * sv.x + coef * av.x);
        st.y = scale * (sgn * sv.y + coef * av.y);
        st.z = scale * (sgn * sv.z + coef * av.z);
        st.w = scale * (sgn * sv.w + coef * av.w);
        *(float4*)&C[go] = st;
    }
}

// ====== mma kernel 3: batched C[rows x 64] = A[rows x K] @ B[K x 64] =======
// register-prefetch double buffered
__global__ void k_b64_mma(const float* __restrict__ A, size_t sA, int lda,
                          const float* __restrict__ B, size_t sB,
                          float* __restrict__ C, size_t sC, int K)
{
    extern __shared__ float smf[];
    float* As = smf;
    float* Bs = As + 128 * AST;
    int tid = threadIdx.x, wid = tid >> 5;
    int wm = wid >> 1, wn = wid & 1;               // 4x2 warps, warp tile 32x32
    int bh = blockIdx.y;
    int row0 = blockIdx.x * 128;
    const float* Ab = A + (size_t)bh * sA;
    const float* Bb = B + (size_t)bh * sB;
    float* Cb = C + (size_t)bh * sC;
    int ra = tid >> 3, fa = tid & 7;
    int kb_ = tid >> 4, cb = tid & 15;             // B: 2 k-rows via +16

    wmma::fragment<wmma::accumulator, 16, 16, 8, float> acc[2][2];
#pragma unroll
    for (int mf = 0; mf < 2; mf++)
#pragma unroll
        for (int nf = 0; nf < 2; nf++) wmma::fill_fragment(acc[mf][nf], 0.f);

    float4 pa[4], pb[2];
#pragma unroll
    for (int i = 0; i < 4; i++)
        pa[i] = *(const float4*)&Ab[(size_t)(row0 + ra + i * 32) * lda + fa * 4];
#pragma unroll
    for (int i = 0; i < 2; i++)
        pb[i] = *(const float4*)&Bb[(size_t)(kb_ + i * 16) * 64 + cb * 4];

    int NC = K / 32;
    for (int ci = 0; ci < NC; ci++) {
#pragma unroll
        for (int i = 0; i < 4; i++) *(float4*)&As[(ra + i * 32) * AST + fa * 4] = pa[i];
#pragma unroll
        for (int i = 0; i < 2; i++) *(float4*)&Bs[(kb_ + i * 16) * B64ST + cb * 4] = pb[i];
        __syncthreads();
        if (ci + 1 < NC) {
            int k0 = (ci + 1) * 32;
#pragma unroll
            for (int i = 0; i < 4; i++)
                pa[i] = *(const float4*)&Ab[(size_t)(row0 + ra + i * 32) * lda + k0 + fa * 4];
#pragma unroll
            for (int i = 0; i < 2; i++)
                pb[i] = *(const float4*)&Bb[(size_t)(k0 + kb_ + i * 16) * 64 + cb * 4];
        }
#pragma unroll
        for (int ks = 0; ks < 4; ks++) {
            wmma::fragment<wmma::matrix_b, 16, 16, 8, wmma::precision::tf32, wmma::row_major> bf[2];
#pragma unroll
            for (int nf = 0; nf < 2; nf++) {
                wmma::load_matrix_sync(bf[nf], Bs + (ks * 8) * B64ST + wn * 32 + nf * 16, B64ST);
                CVT_FRAG(bf[nf]);
            }
#pragma unroll
            for (int mf = 0; mf < 2; mf++) {
                wmma::fragment<wmma::matrix_a, 16, 16, 8, wmma::precision::tf32, wmma::row_major> af;
                wmma::load_matrix_sync(af, As + (wm * 32 + mf * 16) * AST + ks * 8, AST);
                CVT_FRAG(af);
#pragma unroll
                for (int nf = 0; nf < 2; nf++) wmma::mma_sync(acc[mf][nf], af, bf[nf], acc[mf][nf]);
            }
        }
        __syncthreads();
    }
#pragma unroll
    for (int mf = 0; mf < 2; mf++)
#pragma unroll
        for (int nf = 0; nf < 2; nf++)
            wmma::store_matrix_sync(&Cb[(size_t)(row0 + wm * 32 + mf * 16) * 64 + wn * 32 + nf * 16],
                                    acc[mf][nf], 64, wmma::mem_row_major);
}

// ============ mma kernel 4: out = gather(outh) @ Wout (M=16384) ============
// register-prefetch double buffered
__global__ void k_final_mma(const float* __restrict__ outh, const float* __restrict__ W,
                            float* __restrict__ out)
{
    extern __shared__ float smf[];
    float* As = smf;
    float* Bs = As + 128 * AST;
    int tid = threadIdx.x, wid = tid >> 5;
    int wm = wid >> 2, wn = wid & 3;
    int row0 = blockIdx.y * 128, col0 = blockIdx.x * 128;
    int ra = tid >> 3, fa = tid & 7;
    int kb_ = tid >> 5, cb = tid & 31;

    wmma::fragment<wmma::accumulator, 16, 16, 8, float> acc[4][2];
#pragma unroll
    for (int mf = 0; mf < 4; mf++)
#pragma unroll
        for (int nf = 0; nf < 2; nf++) wmma::fill_fragment(acc[mf][nf], 0.f);

    float4 pa[4], pb[4];
    {
#pragma unroll
        for (int i = 0; i < 4; i++) {
            int rg = row0 + ra + i * 32;
            int b = rg >> 12, n = rg & 4095;
            int kg = fa * 4;
            int h = kg >> 6, d = kg & 63;
            pa[i] = *(const float4*)&outh[((size_t)(b * 8 + h) * 4096 + n) * 64 + d];
            pb[i] = *(const float4*)&W[(size_t)(kb_ + i * 8) * 512 + col0 + cb * 4];
        }
    }
    for (int ci = 0; ci < 16; ci++) {
#pragma unroll
        for (int i = 0; i < 4; i++) {
            *(float4*)&As[(ra + i * 32) * AST + fa * 4] = pa[i];
            *(float4*)&Bs[(kb_ + i * 8) * BST + cb * 4] = pb[i];
        }
        __syncthreads();
        if (ci < 15) {
            int k0 = (ci + 1) * 32;
#pragma unroll
            for (int i = 0; i < 4; i++) {
                int rg = row0 + ra + i * 32;
                int b = rg >> 12, n = rg & 4095;
                int kg = k0 + fa * 4;
                int h = kg >> 6, d = kg & 63;
                pa[i] = *(const float4*)&outh[((size_t)(b * 8 + h) * 4096 + n) * 64 + d];
                pb[i] = *(const float4*)&W[(size_t)(k0 + kb_ + i * 8) * 512 + col0 + cb * 4];
            }
        }
#pragma unroll
        for (int ks = 0; ks < 4; ks++) {
            wmma::fragment<wmma::matrix_b, 16, 16, 8, wmma::precision::tf32, wmma::row_major> bf[2];
#pragma unroll
            for (int nf = 0; nf < 2; nf++) {
                wmma::load_matrix_sync(bf[nf], Bs + (ks * 8) * BST + wn * 32 + nf * 16, BST);
                CVT_FRAG(bf[nf]);
            }
#pragma unroll
            for (int mf = 0; mf < 4; mf++) {
                wmma::fragment<wmma::matrix_a, 16, 16, 8, wmma::precision::tf32, wmma::row_major> af;
                wmma::load_matrix_sync(af, As + (wm * 64 + mf * 16) * AST + ks * 8, AST);
                CVT_FRAG(af);
#pragma unroll
                for (int nf = 0; nf < 2; nf++) wmma::mma_sync(acc[mf][nf], af, bf[nf], acc[mf][nf]);
            }
        }
        __syncthreads();
    }
#pragma unroll
    for (int mf = 0; mf < 4; mf++)
#pragma unroll
        for (int nf = 0; nf < 2; nf++)
            wmma::store_matrix_sync(&out[(size_t)(row0 + wm * 64 + mf * 16) * 512 + col0 + wn * 32 + nf * 16],
                                    acc[mf][nf], 512, wmma::mem_row_major);
}

// ===== fused kernel A: outh = softmax(q@kl^T) @ tmp2 + conv(v), per 64 rows =
__global__ void k_attn1_out(const float* __restrict__ Q, const float* __restrict__ KL,
                            const float* __restrict__ T2, const float* __restrict__ V,
                            const float* __restrict__ wres, float* __restrict__ outh)
{
    extern __shared__ float smf[];
    float* qv = smf;                 // 96*72: q tile (64 x ld72), later v halo (96x64)
    float* kb = smf + 96 * 72;       // 256*72: kl (col data), later tmp2
    float* S  = kb + 256 * 72;       // 64*264: scores / later output staging (ld 72)
    __shared__ float wc[33];
    int tid = threadIdx.x, wid = tid >> 5, lane = tid & 31;
    int bh = blockIdx.y, row0 = blockIdx.x * 64;
    if (tid < 33) wc[tid] = wres[(bh & 7) * 33 + tid];

    const float* Qb = Q + ((size_t)bh * NN + row0) * 64;
    for (int i = tid; i < 64 * 16; i += 256) {
        int r = i >> 4, f = i & 15;
        *(float4*)&qv[r * 72 + f * 4] = *(const float4*)&Qb[(size_t)r * 64 + f * 4];
    }
    const float* Kb = KL + (size_t)bh * MM * 64;
    for (int i = tid; i < 256 * 16; i += 256) {
        int r = i >> 4, f = i & 15;
        *(float4*)&kb[r * 72 + f * 4] = *(const float4*)&Kb[(size_t)r * 64 + f * 4];
    }
    __syncthreads();

    // GEMM1: S(64x256) = q @ kl^T  (3xTF32; warps 2x4, warp tile 32x64)
    {
        int wm = wid >> 2, wn = wid & 3;
        wmma::fragment<wmma::accumulator, 16, 16, 8, float> a1[2][4];
#pragma unroll
        for (int mf = 0; mf < 2; mf++)
#pragma unroll
            for (int nf = 0; nf < 4; nf++) wmma::fill_fragment(a1[mf][nf], 0.f);
#pragma unroll
        for (int ks = 0; ks < 8; ks++) {
            wmma::fragment<wmma::matrix_b, 16, 16, 8, wmma::precision::tf32, wmma::col_major> bh_[4], bl_[4];
#pragma unroll
            for (int nf = 0; nf < 4; nf++) {
                wmma::fragment<wmma::matrix_b, 16, 16, 8, wmma::precision::tf32, wmma::col_major> braw;
                wmma::load_matrix_sync(braw, kb + (wn * 64 + nf * 16) * 72 + ks * 8, 72);
                split_frag(bh_[nf], bl_[nf], braw);
            }
#pragma unroll
            for (int mf = 0; mf < 2; mf++) {
                wmma::fragment<wmma::matrix_a, 16, 16, 8, wmma::precision::tf32, wmma::row_major> araw, ah, al;
                wmma::load_matrix_sync(araw, qv + (wm * 32 + mf * 16) * 72 + ks * 8, 72);
                split_frag(ah, al, araw);
#pragma unroll
                for (int nf = 0; nf < 4; nf++) {
                    wmma::mma_sync(a1[mf][nf], ah, bl_[nf], a1[mf][nf]);
                    wmma::mma_sync(a1[mf][nf], al, bh_[nf], a1[mf][nf]);
                    wmma::mma_sync(a1[mf][nf], ah, bh_[nf], a1[mf][nf]);
                }
            }
        }
#pragma unroll
        for (int mf = 0; mf < 2; mf++)
#pragma unroll
            for (int nf = 0; nf < 4; nf++)
                wmma::store_matrix_sync(S + (wm * 32 + mf * 16) * 264 + wn * 64 + nf * 16,
                                        a1[mf][nf], 264, wmma::mem_row_major);
    }
    __syncthreads();

    // softmax rows (warp wid owns rows wid*8..+7; lane group of 4 per row)
    {
        int r = wid * 8 + (lane >> 2);
        float* row = S + r * 264 + (lane & 3) * 64;
        float4 vv[16];
        float m = -FLT_MAX;
#pragma unroll
        for (int f = 0; f < 16; f++) {
            vv[f] = *(float4*)&row[f * 4];
            m = fmaxf(m, fmaxf(fmaxf(vv[f].x, vv[f].y), fmaxf(vv[f].z, vv[f].w)));
        }
        m = fmaxf(m, __shfl_xor_sync(0xffffffffu, m, 1));
        m = fmaxf(m, __shfl_xor_sync(0xffffffffu, m, 2));
        float s = 0.f;
#pragma unroll
        for (int f = 0; f < 16; f++) {
            vv[f].x = expf(vv[f].x - m); vv[f].y = expf(vv[f].y - m);
            vv[f].z = expf(vv[f].z - m); vv[f].w = expf(vv[f].w - m);
            s += vv[f].x + vv[f].y + vv[f].z + vv[f].w;
        }
        s += __shfl_xor_sync(0xffffffffu, s, 1);
        s += __shfl_xor_sync(0xffffffffu, s, 2);
        float inv = 1.f / s;
#pragma unroll
        for (int f = 0; f < 16; f++) {
            vv[f].x *= inv; vv[f].y *= inv; vv[f].z *= inv; vv[f].w *= inv;
            *(float4*)&row[f * 4] = vv[f];
        }
    }
    __syncthreads();

    // reload kb with tmp2, qv with v halo
    const float* Tb = T2 + (size_t)bh * MM * 64;
    for (int i = tid; i < 256 * 16; i += 256) {
        int r = i >> 4, f = i & 15;
        *(float4*)&kb[r * 72 + f * 4] = *(const float4*)&Tb[(size_t)r * 64 + f * 4];
    }
    for (int i = tid; i < 96 * 64; i += 256) {
        int rr = i >> 6, d = i & 63;
        int n = row0 + rr - 16;
        qv[rr * 64 + d] = (n >= 0 && n < NN) ? V[((size_t)bh * NN + n) * 64 + d] : 0.f;
    }
    __syncthreads();

    // GEMM2: O(64x64) = P(64x256) @ tmp2(256x64)  (warps 4x2, warp tile 16x32)
    int wm2 = wid >> 1, wn2 = wid & 1;
    wmma::fragment<wmma::accumulator, 16, 16, 8, float> a2[2];
#pragma unroll
    for (int nf = 0; nf < 2; nf++) wmma::fill_fragment(a2[nf], 0.f);
#pragma unroll 8
    for (int ks = 0; ks < 32; ks++) {
        wmma::fragment<wmma::matrix_a, 16, 16, 8, wmma::precision::tf32, wmma::row_major> af;
        wmma::load_matrix_sync(af, S + (wm2 * 16) * 264 + ks * 8, 264);
        CVT_FRAG(af);
#pragma unroll
        for (int nf = 0; nf < 2; nf++) {
            wmma::fragment<wmma::matrix_b, 16, 16, 8, wmma::precision::tf32, wmma::row_major> bf;
            wmma::load_matrix_sync(bf, kb + (ks * 8) * 72 + wn2 * 32 + nf * 16, 72);
            CVT_FRAG(bf);
            wmma::mma_sync(a2[nf], af, bf, a2[nf]);
        }
    }
    __syncthreads();   // all P reads done before overwriting S
#pragma unroll
    for (int nf = 0; nf < 2; nf++)
        wmma::store_matrix_sync(S + (wm2 * 16) * 72 + wn2 * 32 + nf * 16, a2[nf], 72, wmma::mem_row_major);
    __syncthreads();

    // conv residual + write
    for (int i = tid; i < 64 * 16; i += 256) {
        int r = i >> 4, c = (i & 15) * 4;
        float4 o = *(float4*)&S[r * 72 + c];
#pragma unroll 1
        for (int t = 0; t < 33; t++) {
            float w = wc[t];
            float4 vb = *(float4*)&qv[(r + t) * 64 + c];
            o.x += w * vb.x; o.y += w * vb.y; o.z += w * vb.z; o.w += w * vb.w;
        }
        *(float4*)&outh[((size_t)bh * NN + row0 + r) * 64 + c] = o;
    }
}

// ===== fused kernel B: tmp1 = softmax(ql @ k^T) @ v  (flash-style) =========
// QK logits 3xTF32; PV on tensor cores (tf32) with smem-staged rescale.
__global__ void k_flash3(const float* __restrict__ QL, const float* __restrict__ K,
                         const float* __restrict__ V, float* __restrict__ tmp1)
{
    extern __shared__ float smf[];
    float* qs = smf;                 // 64*72
    float* kt = qs + 64 * 72;        // 128*72
    float* vt = kt + 128 * 72;       // 128*72
    float* S  = vt + 128 * 72;       // 64*136
    int tid = threadIdx.x, wid = tid >> 5, lane = tid & 31;
    int bh = blockIdx.y, row0 = blockIdx.x * 64;

    const float* Qb = QL + ((size_t)bh * MM + row0) * 64;
    for (int i = tid; i < 64 * 16; i += 256) {
        int r = i >> 4, f = i & 15;
        *(float4*)&qs[r * 72 + f * 4] = *(const float4*)&Qb[(size_t)r * 64 + f * 4];
    }

    int r_loc = wid * 8 + (lane >> 2);         // this lane's row (4 lanes per row)
    int c0s = (lane & 3) * 32;                 // softmax chunk (32 cols of 128)
    int c0v = (lane & 3) * 16;                 // output chunk (16 cols of 64)
    float mrow = -1e30f, lrow = 0.f;
    float o[16];
#pragma unroll
    for (int i = 0; i < 16; i++) o[i] = 0.f;

    int wm = wid >> 2, wn = wid & 3;           // QK warp layout 2x4, warp tile 32x32
    int wm2 = wid >> 1, wn2 = wid & 1;         // PV warp layout 4x2, warp tile 16x32

    for (int nt = 0; nt < 32; nt++) {
        __syncthreads();   // prev tile's S/vt reads done
        const float* Kb = K + ((size_t)bh * NN + nt * 128) * 64;
        const float* Vb = V + ((size_t)bh * NN + nt * 128) * 64;
        for (int i = tid; i < 128 * 16; i += 256) {
            int r = i >> 4, f = i & 15;
            *(float4*)&kt[r * 72 + f * 4] = *(const float4*)&Kb[(size_t)r * 64 + f * 4];
            *(float4*)&vt[r * 72 + f * 4] = *(const float4*)&Vb[(size_t)r * 64 + f * 4];
        }
        __syncthreads();

        // S(64x128) = ql @ k^T  (3xTF32)
        wmma::fragment<wmma::accumulator, 16, 16, 8, float> a1[2][2];
#pragma unroll
        for (int mf = 0; mf < 2; mf++)
#pragma unroll
            for (int nf = 0; nf < 2; nf++) wmma::fill_fragment(a1[mf][nf], 0.f);
#pragma unroll
        for (int ks = 0; ks < 8; ks++) {
            wmma::fragment<wmma::matrix_b, 16, 16, 8, wmma::precision::tf32, wmma::col_major> bh_[2], bl_[2];
#pragma unroll
            for (int nf = 0; nf < 2; nf++) {
                wmma::fragment<wmma::matrix_b, 16, 16, 8, wmma::precision::tf32, wmma::col_major> braw;
                wmma::load_matrix_sync(braw, kt + (wn * 32 + nf * 16) * 72 + ks * 8, 72);
                split_frag(bh_[nf], bl_[nf], braw);
            }
#pragma unroll
            for (int mf = 0; mf < 2; mf++) {
                wmma::fragment<wmma::matrix_a, 16, 16, 8, wmma::precision::tf32, wmma::row_major> araw, ah, al;
                wmma::load_matrix_sync(araw, qs + (wm * 32 + mf * 16) * 72 + ks * 8, 72);
                split_frag(ah, al, araw);
#pragma unroll
                for (int nf = 0; nf < 2; nf++) {
                    wmma::mma_sync(a1[mf][nf], ah, bl_[nf], a1[mf][nf]);
                    wmma::mma_sync(a1[mf][nf], al, bh_[nf], a1[mf][nf]);
                    wmma::mma_sync(a1[mf][nf], ah, bh_[nf], a1[mf][nf]);
                }
            }
        }
#pragma unroll
        for (int mf = 0; mf < 2; mf++)
#pragma unroll
            for (int nf = 0; nf < 2; nf++)
                wmma::store_matrix_sync(S + (wm * 32 + mf * 16) * 136 + wn * 32 + nf * 16,
                                        a1[mf][nf], 136, wmma::mem_row_major);
        __syncthreads();   // softmax reads S rows written by other warps

        // online softmax update (each warp owns 8 rows; 4 lanes per row)
        float ef;
        {
            float* srow = S + r_loc * 136 + c0s;
            float4 pv[8];
            float tm = -1e30f;
#pragma unroll
            for (int f = 0; f < 8; f++) {
                pv[f] = *(float4*)&srow[f * 4];
                tm = fmaxf(tm, fmaxf(fmaxf(pv[f].x, pv[f].y), fmaxf(pv[f].z, pv[f].w)));
            }
            tm = fmaxf(tm, __shfl_xor_sync(0xffffffffu, tm, 1));
            tm = fmaxf(tm, __shfl_xor_sync(0xffffffffu, tm, 2));
            float nm = fmaxf(mrow, tm);
            ef = expf(mrow - nm);
            float ts = 0.f;
#pragma unroll
            for (int f = 0; f < 8; f++) {
                pv[f].x = expf(pv[f].x - nm); pv[f].y = expf(pv[f].y - nm);
                pv[f].z = expf(pv[f].z - nm); pv[f].w = expf(pv[f].w - nm);
                ts += pv[f].x + pv[f].y + pv[f].z + pv[f].w;
                *(float4*)&srow[f * 4] = pv[f];
            }
            ts += __shfl_xor_sync(0xffffffffu, ts, 1);
            ts += __shfl_xor_sync(0xffffffffu, ts, 2);
            lrow = lrow * ef + ts;
            mrow = nm;
        }
        __syncthreads();   // PV mma below reads all P rows

        // PV: Opart(64x64) = P(64x128) @ V(128x64) on tensor cores
        wmma::fragment<wmma::accumulator, 16, 16, 8, float> apv[2];
#pragma unroll
        for (int nf = 0; nf < 2; nf++) wmma::fill_fragment(apv[nf], 0.f);
#pragma unroll
        for (int ks = 0; ks < 16; ks++) {
            wmma::fragment<wmma::matrix_a, 16, 16, 8, wmma::precision::tf32, wmma::row_major> af;
            wmma::load_matrix_sync(af, S + (wm2 * 16) * 136 + ks * 8, 136);
            CVT_FRAG(af);
#pragma unroll
            for (int nf = 0; nf < 2; nf++) {
                wmma::fragment<wmma::matrix_b, 16, 16, 8, wmma::precision::tf32, wmma::row_major> bf;
                wmma::load_matrix_sync(bf, vt + (ks * 8) * 72 + wn2 * 32 + nf * 16, 72);
                CVT_FRAG(bf);
                wmma::mma_sync(apv[nf], af, bf, apv[nf]);
            }
        }
        __syncthreads();   // all P reads done before staging overwrites S
#pragma unroll
        for (int nf = 0; nf < 2; nf++)
            wmma::store_matrix_sync(S + (wm2 * 16) * 136 + wn2 * 32 + nf * 16,
                                    apv[nf], 136, wmma::mem_row_major);
        __syncthreads();   // staging visible to all

        // o = o*ef + Opart  (16 cols per lane)
        {
            const float* prow = S + r_loc * 136 + c0v;
#pragma unroll
            for (int cc = 0; cc < 4; cc++) {
                float4 po = *(const float4*)&prow[cc * 4];
                o[cc*4+0] = o[cc*4+0] * ef + po.x;
                o[cc*4+1] = o[cc*4+1] * ef + po.y;
                o[cc*4+2] = o[cc*4+2] * ef + po.z;
                o[cc*4+3] = o[cc*4+3] * ef + po.w;
            }
        }
    }

    float inv = 1.f / lrow;
    float* orow = tmp1 + ((size_t)bh * MM + row0 + r_loc) * 64 + c0v;
#pragma unroll
    for (int cc = 0; cc < 4; cc++) {
        float4 st = {o[cc*4] * inv, o[cc*4+1] * inv, o[cc*4+2] * inv, o[cc*4+3] * inv};
        *(float4*)&orow[cc * 4] = st;
    }
}

// ================= fp32 kernels (landmarks, sim2, pinv prep) ===============
__global__ void k_land(const float* __restrict__ q, const float* __restrict__ k,
                       float* __restrict__ ql, float* __restrict__ kl)
{
    int idx = blockIdx.x * 256 + threadIdx.x;
    int d = idx & 63;
    int m = (idx >> 6) & 255;
    int bh = idx >> 14;
    size_t base = ((size_t)bh * NN + m * LL) * DH + d;
    float sq = 0.f, sk = 0.f;
#pragma unroll
    for (int i = 0; i < LL; i++) { sq += q[base + (size_t)i * DH]; sk += k[base + (size_t)i * DH]; }
    ql[idx] = sq * (1.f / LL);
    kl[idx] = sk * (1.f / LL);
}

__global__ void k_sim_softmax(const float* __restrict__ Q, const float* __restrict__ KL,
                              float* __restrict__ Out, int nrows)
{
    extern __shared__ float smf[];
    float* ks = smf;
    float* qs = smf + 256 * 65;
    int tid = threadIdx.x;
    int bh = blockIdx.y;
    int row0 = blockIdx.x * 64;
    const float* Qb = Q + ((size_t)bh * nrows + row0) * DH;
    const float* Kb = KL + (size_t)bh * MM * DH;
    for (int i = tid; i < 256 * 64; i += 256) { int c = i >> 6, d = i & 63; ks[c * 65 + d] = Kb[i]; }
    for (int i = tid; i < 64 * 64;  i += 256) { int r = i >> 6, d = i & 63; qs[r * 65 + d] = Qb[i]; }
    __syncthreads();
    int tx = tid & 31, ty = tid >> 5;
    int c1 = tx * 4, c2 = 128 + tx * 4;
    float acc[8][8] = {};
#pragma unroll 4
    for (int d = 0; d < 64; d++) {
        float a_[8];
#pragma unroll
        for (int i = 0; i < 8; i++) a_[i] = qs[(ty * 8 + i) * 65 + d];
        float b_[8];
#pragma unroll
        for (int j = 0; j < 4; j++) { b_[j] = ks[(c1 + j) * 65 + d]; b_[4 + j] = ks[(c2 + j) * 65 + d]; }
#pragma unroll
        for (int i = 0; i < 8; i++)
#pragma unroll
            for (int j = 0; j < 8; j++) acc[i][j] += a_[i] * b_[j];
    }
#pragma unroll
    for (int i = 0; i < 8; i++) {
        float m = acc[i][0];
#pragma unroll
        for (int j = 1; j < 8; j++) m = fmaxf(m, acc[i][j]);
        for (int o = 16; o > 0; o >>= 1) m = fmaxf(m, __shfl_xor_sync(0xffffffffu, m, o));
        float s = 0.f;
#pragma unroll
        for (int j = 0; j < 8; j++) { float e = expf(acc[i][j] - m); acc[i][j] = e; s += e; }
        for (int o = 16; o > 0; o >>= 1) s += __shfl_xor_sync(0xffffffffu, s, o);
        float inv = 1.f / s;
        float* orow = Out + ((size_t)bh * nrows + row0 + ty * 8 + i) * MM;
        float4 w1 = {acc[i][0] * inv, acc[i][1] * inv, acc[i][2] * inv, acc[i][3] * inv};
        float4 w2 = {acc[i][4] * inv, acc[i][5] * inv, acc[i][6] * inv, acc[i][7] * inv};
        *(float4*)(orow + c1) = w1;
        *(float4*)(orow + c2) = w2;
    }
}

// coalesced two-pass reduction: max col-abs-sum and max row-abs-sum
__global__ void k_pinv_prep(const float* __restrict__ X, int* red)
{
    __shared__ float sred[16];
    int bh = blockIdx.x;
    int tid = threadIdx.x, wid = tid >> 5, lane = tid & 31;
    const float* Xb = X + (size_t)bh * MM * MM;

    // pass 1: thread j accumulates sum_i |X[i][j]| (coalesced across j)
    float cs = 0.f;
    for (int i = 0; i < MM; i++) cs += fabsf(Xb[(size_t)i * MM + tid]);
    // pass 2: warp w handles rows w, w+8, ...; lanes stride the row (coalesced)
    float rmax = 0.f;
    for (int row = wid; row < MM; row += 8) {
        float s = 0.f;
        const float* rp = Xb + (size_t)row * MM;
#pragma unroll
        for (int f = 0; f < 8; f++) s += fabsf(rp[lane + f * 32]);
        for (int o = 16; o > 0; o >>= 1) s += __shfl_xor_sync(0xffffffffu, s, o);
        rmax = fmaxf(rmax, s);
    }
    // block-reduce max(cs) and max(rmax)
    for (int o = 16; o > 0; o >>= 1) cs = fmaxf(cs, __shfl_xor_sync(0xffffffffu, cs, o));
    if (lane == 0) { sred[wid] = cs; sred[8 + wid] = rmax; }
    __syncthreads();
    if (wid == 0) {
        float a = (lane < 8) ? sred[lane] : 0.f;
        float b = (lane < 8) ? sred[8 + lane] : 0.f;
        for (int o = 16; o > 0; o >>= 1) {
            a = fmaxf(a, __shfl_xor_sync(0xffffffffu, a, o));
            b = fmaxf(b, __shfl_xor_sync(0xffffffffu, b, o));
        }
        if (lane == 0) {
            atomicMax(&red[0], __float_as_int(a));
            atomicMax(&red[1], __float_as_int(b));
        }
    }
}

__global__ void k_zinit(const float* __restrict__ X, float* __restrict__ Z, const int* red)
{
    float denom = __int_as_float(red[0]) * __int_as_float(red[1]) + 1e-8f;
    int idx = blockIdx.x * 256 + threadIdx.x;
    int bh = idx >> 16;
    int rem = idx & 65535;
    int i = rem >> 8, j = rem & 255;
    Z[idx] = X[((size_t)bh << 16) + j * MM + i] / denom;
}

// --------------------------- host launcher --------------------------------
extern "C" void kernel_launch(void* const* d_in, const int* in_sizes, int n_in,
                              void* d_out, int out_size)
{
    const float *x = nullptr, *wqkv = nullptr, *wout = nullptr, *wres = nullptr;
    for (int i = 0; i < n_in; i++) {
        switch (in_sizes[i]) {
            case 8388608: x = (const float*)d_in[i]; break;
            case 786432:  wqkv = (const float*)d_in[i]; break;
            case 262144:  wout = (const float*)d_in[i]; break;
            case 264:     wres = (const float*)d_in[i]; break;
            default: break;
        }
    }

    float *pq, *pk, *pv, *pql, *pkl, *pattn2;
    float *pzA, *pzB, *pxz, *pt, *pu, *ptmp1, *ptmp2, *pouth;
    int* pred;
    cudaGetSymbolAddress((void**)&pq, g_q);
    cudaGetSymbolAddress((void**)&pk, g_k);
    cudaGetSymbolAddress((void**)&pv, g_v);
    cudaGetSymbolAddress((void**)&pql, g_ql);
    cudaGetSymbolAddress((void**)&pkl, g_kl);
    cudaGetSymbolAddress((void**)&pattn2, g_attn2);
    cudaGetSymbolAddress((void**)&pzA, g_zA);
    cudaGetSymbolAddress((void**)&pzB, g_zB);
    cudaGetSymbolAddress((void**)&pxz, g_xz);
    cudaGetSymbolAddress((void**)&pt, g_t);
    cudaGetSymbolAddress((void**)&pu, g_u);
    cudaGetSymbolAddress((void**)&ptmp1, g_tmp1);
    cudaGetSymbolAddress((void**)&ptmp2, g_tmp2);
    cudaGetSymbolAddress((void**)&pouth, g_outh);
    cudaGetSymbolAddress((void**)&pred, g_red);

    size_t shmem_sim = (size_t)(256 + 64) * 65 * sizeof(float);                     // 83200
    const int SM_BIG  = (128 * AST + 32 * BST + 128 * SST) * sizeof(float);         // 107520
    const int SM_FIN  = (128 * AST + 32 * BST) * sizeof(float);                     // 37888
    const int SM_B64  = (128 * AST + 32 * B64ST) * sizeof(float);                   // 29696
    const int SM_AOUT = (96 * 72 + 256 * 72 + 64 * 264) * sizeof(float);            // 168960
    const int SM_FLSH = (64 * 72 + 128 * 72 + 128 * 72 + 64 * 136) * sizeof(float); // 126976
    cudaFuncSetAttribute(k_sim_softmax, cudaFuncAttributeMaxDynamicSharedMemorySize, (int)shmem_sim);
    cudaFuncSetAttribute(k_qkv_mma, cudaFuncAttributeMaxDynamicSharedMemorySize, SM_BIG);
    cudaFuncSetAttribute(k_g256_mma, cudaFuncAttributeMaxDynamicSharedMemorySize, SM_BIG);
    cudaFuncSetAttribute(k_final_mma, cudaFuncAttributeMaxDynamicSharedMemorySize, SM_FIN);
    cudaFuncSetAttribute(k_b64_mma, cudaFuncAttributeMaxDynamicSharedMemorySize, SM_B64);
    cudaFuncSetAttribute(k_attn1_out, cudaFuncAttributeMaxDynamicSharedMemorySize, SM_AOUT);
    cudaFuncSetAttribute(k_flash3, cudaFuncAttributeMaxDynamicSharedMemorySize, SM_FLSH);

    // second stream + fork/join events (host objects only; capture-legal)
    cudaStream_t s1;
    cudaStreamCreate(&s1);
    cudaEvent_t evLand, evFlash;
    cudaEventCreateWithFlags(&evLand, cudaEventDisableTiming);
    cudaEventCreateWithFlags(&evFlash, cudaEventDisableTiming);

    // 1) qkv projection + head scatter (s0)
    k_qkv_mma<<<dim3(12, 128), 256, SM_BIG>>>(x, wqkv, pq, pk, pv);
    // 2) landmarks (s0)
    k_land<<<2048, 256>>>(pq, pk, pql, pkl);
    cudaEventRecord(evLand, 0);

    // fork: flash3 on s1 (needs ql, k, v only) — overlaps with the pinv chain
    cudaStreamWaitEvent(s1, evLand, 0);
    k_flash3<<<dim3(4, BH), 256, SM_FLSH, s1>>>(pql, pk, pv, ptmp1);
    cudaEventRecord(evFlash, s1);

    // 3) sim2 + softmax (s0)
    k_sim_softmax<<<dim3(4, BH), 256, shmem_sim>>>(pql, pkl, pattn2, MM);
    // 4) pinv init (s0)
    cudaMemsetAsync(pred, 0, 2 * sizeof(int));
    k_pinv_prep<<<BH, 256>>>(pattn2, pred);
    k_zinit<<<8192, 256>>>(pattn2, pzA, pred);
    // 5) 6 Newton-Schulz iterations (s0)
    float* zp = pzA;
    float* z2p = pzB;
    for (int it = 0; it < 6; it++) {
        k_g256_mma<<<dim3(2, 2, BH), 256, SM_BIG>>>(pattn2, zp, pxz, 0.f, 1.f, 1.f);
        k_g256_mma<<<dim3(2, 2, BH), 256, SM_BIG>>>(pxz, pxz, pt, 7.f, -1.f, 1.f);
        k_g256_mma<<<dim3(2, 2, BH), 256, SM_BIG>>>(pxz, pt, pu, 15.f, -1.f, 1.f);
        k_g256_mma<<<dim3(2, 2, BH), 256, SM_BIG>>>(zp, pu, z2p, 13.f, -1.f, 0.25f);
        float* sw = zp; zp = z2p; z2p = sw;
    }
    // join: b64 needs z (s0 chain) and tmp1 (s1 flash3)
    cudaStreamWaitEvent(0, evFlash, 0);
    // 7) tmp2 = z @ tmp1 (K = 256)
    k_b64_mma<<<dim3(2, BH), 256, SM_B64>>>(zp, (size_t)MM * MM, MM,
                                            ptmp1, (size_t)MM * DH, ptmp2, (size_t)MM * DH, MM);
    // 8) outh = softmax(q @ kl^T) @ tmp2 + conv(v)
    k_attn1_out<<<dim3(64, BH), 256, SM_AOUT>>>(pq, pkl, ptmp2, pv, wres, pouth);
    // 9) out = reshape(outh) @ w_out
    k_final_mma<<<dim3(4, 128), 256, SM_FIN>>>(pouth, wout, (float*)d_out);
}

// round 14
// speedup vs baseline: 1.6695x; 1.0192x over previous
#include <cuda_runtime.h>
#include <float.h>
#include <cstdint>
#include <mma.h>
using namespace nvcuda;

#define BB 4
#define NN 4096
#define DIMD 512
#define HH 8
#define DH 64
#define MM 256
#define LL 16
#define BH (BB*HH)          // 32

// ------------------- scratch (device globals; no allocs) -------------------
__device__ float g_q[BH*NN*DH];
__device__ float g_k[BH*NN*DH];
__device__ float g_v[BH*NN*DH];
__device__ float g_ql[BH*MM*DH];
__device__ float g_kl[BH*MM*DH];
__device__ float g_attn2[BH*MM*MM];
__device__ float g_zA[BH*MM*MM];
__device__ float g_zB[BH*MM*MM];
__device__ float g_xz[BH*MM*MM];
__device__ float g_t[BH*MM*MM];
__device__ float g_u[BH*MM*MM];
__device__ float g_tmp1[BH*MM*DH];
__device__ float g_tmp2[BH*MM*DH];
__device__ float g_outh[BH*NN*DH];
__device__ int   g_red[2];

// strides (floats) inside dynamic smem
#define AST 40      // A tile stride: [128][40]
#define BST 136     // B tile stride: [32][136]
#define SST 136     // staging stride: [128][136]
#define B64ST 72    // B tile stride for N=64 kernels

#define CVT_FRAG(f) do { for (int _t = 0; _t < (f).num_elements; _t++) (f).x[_t] = wmma::__float_to_tf32((f).x[_t]); } while (0)

// 3xTF32 split: hi = tf32(a), lo = tf32(a - hi)
template <typename Frag>
__device__ __forceinline__ void split_frag(Frag& hi, Frag& lo, const Frag& src) {
#pragma unroll
    for (int t = 0; t < src.num_elements; t++) {
        float h = wmma::__float_to_tf32(src.x[t]);
        hi.x[t] = h;
        lo.x[t] = wmma::__float_to_tf32(src.x[t] - h);
    }
}

// ================== mma kernel 1: qkv = X @ Wqkv, scatter ==================
// register-prefetch double buffered
__global__ void k_qkv_mma(const float* __restrict__ X, const float* __restrict__ W,
                          float* __restrict__ q, float* __restrict__ k, float* __restrict__ v)
{
    extern __shared__ float smf[];
    float* As = smf;
    float* Bs = As + 128 * AST;
    float* St = Bs + 32 * BST;
    int tid = threadIdx.x, wid = tid >> 5;
    int wm = wid >> 2, wn = wid & 3;               // 2x4 warps
    int row0 = blockIdx.y * 128, col0 = blockIdx.x * 128;
    int ra = tid >> 3, fa = tid & 7;               // A: this thread's 4 rows via +32
    int kb_ = tid >> 5, cb = tid & 31;             // B: 4 k-rows via +8

    wmma::fragment<wmma::accumulator, 16, 16, 8, float> acc[4][2];
#pragma unroll
    for (int mf = 0; mf < 4; mf++)
#pragma unroll
        for (int nf = 0; nf < 2; nf++) wmma::fill_fragment(acc[mf][nf], 0.f);

    float4 pa[4], pb[4];
#pragma unroll
    for (int i = 0; i < 4; i++) {
        pa[i] = *(const float4*)&X[(size_t)(row0 + ra + i * 32) * 512 + fa * 4];
        pb[i] = *(const float4*)&W[(size_t)(kb_ + i * 8) * 1536 + col0 + cb * 4];
    }
    for (int ci = 0; ci < 16; ci++) {
#pragma unroll
        for (int i = 0; i < 4; i++) {
            *(float4*)&As[(ra + i * 32) * AST + fa * 4] = pa[i];
            *(float4*)&Bs[(kb_ + i * 8) * BST + cb * 4] = pb[i];
        }
        __syncthreads();
        if (ci < 15) {
            int k0 = (ci + 1) * 32;
#pragma unroll
            for (int i = 0; i < 4; i++) {
                pa[i] = *(const float4*)&X[(size_t)(row0 + ra + i * 32) * 512 + k0 + fa * 4];
                pb[i] = *(const float4*)&W[(size_t)(k0 + kb_ + i * 8) * 1536 + col0 + cb * 4];
            }
        }
#pragma unroll
        for (int ks = 0; ks < 4; ks++) {
            wmma::fragment<wmma::matrix_b, 16, 16, 8, wmma::precision::tf32, wmma::row_major> bf[2];
#pragma unroll
            for (int nf = 0; nf < 2; nf++) {
                wmma::load_matrix_sync(bf[nf], Bs + (ks * 8) * BST + wn * 32 + nf * 16, BST);
                CVT_FRAG(bf[nf]);
            }
#pragma unroll
            for (int mf = 0; mf < 4; mf++) {
                wmma::fragment<wmma::matrix_a, 16, 16, 8, wmma::precision::tf32, wmma::row_major> af;
                wmma::load_matrix_sync(af, As + (wm * 64 + mf * 16) * AST + ks * 8, AST);
                CVT_FRAG(af);
#pragma unroll
                for (int nf = 0; nf < 2; nf++) wmma::mma_sync(acc[mf][nf], af, bf[nf], acc[mf][nf]);
            }
        }
        __syncthreads();
    }
#pragma unroll
    for (int mf = 0; mf < 4; mf++)
#pragma unroll
        for (int nf = 0; nf < 2; nf++)
            wmma::store_matrix_sync(St + (wm * 64 + mf * 16) * SST + wn * 32 + nf * 16,
                                    acc[mf][nf], SST, wmma::mem_row_major);
    __syncthreads();
    for (int i = tid; i < 128 * 32; i += 256) {
        int r = i >> 5, c = (i & 31) * 4;
        float4 val = *(float4*)&St[r * SST + c];
        int rg = row0 + r, b = rg >> 12, n = rg & 4095;
        int cg = col0 + c, which = cg >> 9, h = (cg & 511) >> 6, d = cg & 63;
        float* dst;
        if (which == 0) { val.x *= 0.125f; val.y *= 0.125f; val.z *= 0.125f; val.w *= 0.125f; dst = q; }
        else if (which == 1) dst = k;
        else dst = v;
        *(float4*)&dst[((size_t)(b * 8 + h) * 4096 + n) * 64 + d] = val;
    }
}

// ======== mma kernel 2: batched 256^3  C = scale*(coef*A + sgn*A@B) ========
// register-prefetch double buffered; fragment-wise epilogue (no smem staging)
__global__ void k_g256_mma(const float* __restrict__ A, const float* __restrict__ B,
                           float* __restrict__ C, float coef, float sgn, float scale)
{
    extern __shared__ float smf[];
    float* As = smf;
    float* Bs = As + 128 * AST;
    int tid = threadIdx.x, wid = tid >> 5;
    int wm = wid >> 2, wn = wid & 3;
    size_t base = (size_t)blockIdx.z << 16;
    int row0 = blockIdx.y * 128, col0 = blockIdx.x * 128;
    int ra = tid >> 3, fa = tid & 7;
    int kb_ = tid >> 5, cb = tid & 31;

    wmma::fragment<wmma::accumulator, 16, 16, 8, float> acc[4][2];
#pragma unroll
    for (int mf = 0; mf < 4; mf++)
#pragma unroll
        for (int nf = 0; nf < 2; nf++) wmma::fill_fragment(acc[mf][nf], 0.f);

    float4 pa[4], pb[4];
#pragma unroll
    for (int i = 0; i < 4; i++) {
        pa[i] = *(const float4*)&A[base + (size_t)(row0 + ra + i * 32) * 256 + fa * 4];
        pb[i] = *(const float4*)&B[base + (size_t)(kb_ + i * 8) * 256 + col0 + cb * 4];
    }
    for (int ci = 0; ci < 8; ci++) {
#pragma unroll
        for (int i = 0; i < 4; i++) {
            *(float4*)&As[(ra + i * 32) * AST + fa * 4] = pa[i];
            *(float4*)&Bs[(kb_ + i * 8) * BST + cb * 4] = pb[i];
        }
        __syncthreads();
        if (ci < 7) {
            int k0 = (ci + 1) * 32;
#pragma unroll
            for (int i = 0; i < 4; i++) {
                pa[i] = *(const float4*)&A[base + (size_t)(row0 + ra + i * 32) * 256 + k0 + fa * 4];
                pb[i] = *(const float4*)&B[base + (size_t)(k0 + kb_ + i * 8) * 256 + col0 + cb * 4];
            }
        }
#pragma unroll
        for (int ks = 0; ks < 4; ks++) {
            wmma::fragment<wmma::matrix_b, 16, 16, 8, wmma::precision::tf32, wmma::row_major> bf[2];
#pragma unroll
            for (int nf = 0; nf < 2; nf++) {
                wmma::load_matrix_sync(bf[nf], Bs + (ks * 8) * BST + wn * 32 + nf * 16, BST);
                CVT_FRAG(bf[nf]);
            }
#pragma unroll
            for (int mf = 0; mf < 4; mf++) {
                wmma::fragment<wmma::matrix_a, 16, 16, 8, wmma::precision::tf32, wmma::row_major> af;
                wmma::load_matrix_sync(af, As + (wm * 64 + mf * 16) * AST + ks * 8, AST);
                CVT_FRAG(af);
#pragma unroll
                for (int nf = 0; nf < 2; nf++) wmma::mma_sync(acc[mf][nf], af, bf[nf], acc[mf][nf]);
            }
        }
        __syncthreads();
    }
    // fragment-wise epilogue: C = scale*(sgn*acc + coef*A), accumulator layout
#pragma unroll
    for (int mf = 0; mf < 4; mf++)
#pragma unroll
        for (int nf = 0; nf < 2; nf++) {
            size_t go = base + (size_t)(row0 + wm * 64 + mf * 16) * 256 + col0 + wn * 32 + nf * 16;
            wmma::fragment<wmma::accumulator, 16, 16, 8, float> afr;
            wmma::load_matrix_sync(afr, &A[go], 256, wmma::mem_row_major);
#pragma unroll
            for (int t = 0; t < afr.num_elements; t++)
                acc[mf][nf].x[t] = scale * (sgn * acc[mf][nf].x[t] + coef * afr.x[t]);
            wmma::store_matrix_sync(&C[go], acc[mf][nf], 256, wmma::mem_row_major);
        }
}

// ====== mma kernel 3: batched C[rows x 64] = A[rows x K] @ B[K x 64] =======
// register-prefetch double buffered
__global__ void k_b64_mma(const float* __restrict__ A, size_t sA, int lda,
                          const float* __restrict__ B, size_t sB,
                          float* __restrict__ C, size_t sC, int K)
{
    extern __shared__ float smf[];
    float* As = smf;
    float* Bs = As + 128 * AST;
    int tid = threadIdx.x, wid = tid >> 5;
    int wm = wid >> 1, wn = wid & 1;               // 4x2 warps, warp tile 32x32
    int bh = blockIdx.y;
    int row0 = blockIdx.x * 128;
    const float* Ab = A + (size_t)bh * sA;
    const float* Bb = B + (size_t)bh * sB;
    float* Cb = C + (size_t)bh * sC;
    int ra = tid >> 3, fa = tid & 7;
    int kb_ = tid >> 4, cb = tid & 15;             // B: 2 k-rows via +16

    wmma::fragment<wmma::accumulator, 16, 16, 8, float> acc[2][2];
#pragma unroll
    for (int mf = 0; mf < 2; mf++)
#pragma unroll
        for (int nf = 0; nf < 2; nf++) wmma::fill_fragment(acc[mf][nf], 0.f);

    float4 pa[4], pb[2];
#pragma unroll
    for (int i = 0; i < 4; i++)
        pa[i] = *(const float4*)&Ab[(size_t)(row0 + ra + i * 32) * lda + fa * 4];
#pragma unroll
    for (int i = 0; i < 2; i++)
        pb[i] = *(const float4*)&Bb[(size_t)(kb_ + i * 16) * 64 + cb * 4];

    int NC = K / 32;
    for (int ci = 0; ci < NC; ci++) {
#pragma unroll
        for (int i = 0; i < 4; i++) *(float4*)&As[(ra + i * 32) * AST + fa * 4] = pa[i];
#pragma unroll
        for (int i = 0; i < 2; i++) *(float4*)&Bs[(kb_ + i * 16) * B64ST + cb * 4] = pb[i];
        __syncthreads();
        if (ci + 1 < NC) {
            int k0 = (ci + 1) * 32;
#pragma unroll
            for (int i = 0; i < 4; i++)
                pa[i] = *(const float4*)&Ab[(size_t)(row0 + ra + i * 32) * lda + k0 + fa * 4];
#pragma unroll
            for (int i = 0; i < 2; i++)
                pb[i] = *(const float4*)&Bb[(size_t)(k0 + kb_ + i * 16) * 64 + cb * 4];
        }
#pragma unroll
        for (int ks = 0; ks < 4; ks++) {
            wmma::fragment<wmma::matrix_b, 16, 16, 8, wmma::precision::tf32, wmma::row_major> bf[2];
#pragma unroll
            for (int nf = 0; nf < 2; nf++) {
                wmma::load_matrix_sync(bf[nf], Bs + (ks * 8) * B64ST + wn * 32 + nf * 16, B64ST);
                CVT_FRAG(bf[nf]);
            }
#pragma unroll
            for (int mf = 0; mf < 2; mf++) {
                wmma::fragment<wmma::matrix_a, 16, 16, 8, wmma::precision::tf32, wmma::row_major> af;
                wmma::load_matrix_sync(af, As + (wm * 32 + mf * 16) * AST + ks * 8, AST);
                CVT_FRAG(af);
#pragma unroll
                for (int nf = 0; nf < 2; nf++) wmma::mma_sync(acc[mf][nf], af, bf[nf], acc[mf][nf]);
            }
        }
        __syncthreads();
    }
#pragma unroll
    for (int mf = 0; mf < 2; mf++)
#pragma unroll
        for (int nf = 0; nf < 2; nf++)
            wmma::store_matrix_sync(&Cb[(size_t)(row0 + wm * 32 + mf * 16) * 64 + wn * 32 + nf * 16],
                                    acc[mf][nf], 64, wmma::mem_row_major);
}

// ============ mma kernel 4: out = gather(outh) @ Wout (M=16384) ============
// register-prefetch double buffered
__global__ void k_final_mma(const float* __restrict__ outh, const float* __restrict__ W,
                            float* __restrict__ out)
{
    extern __shared__ float smf[];
    float* As = smf;
    float* Bs = As + 128 * AST;
    int tid = threadIdx.x, wid = tid >> 5;
    int wm = wid >> 2, wn = wid & 3;
    int row0 = blockIdx.y * 128, col0 = blockIdx.x * 128;
    int ra = tid >> 3, fa = tid & 7;
    int kb_ = tid >> 5, cb = tid & 31;

    wmma::fragment<wmma::accumulator, 16, 16, 8, float> acc[4][2];
#pragma unroll
    for (int mf = 0; mf < 4; mf++)
#pragma unroll
        for (int nf = 0; nf < 2; nf++) wmma::fill_fragment(acc[mf][nf], 0.f);

    float4 pa[4], pb[4];
    {
#pragma unroll
        for (int i = 0; i < 4; i++) {
            int rg = row0 + ra + i * 32;
            int b = rg >> 12, n = rg & 4095;
            int kg = fa * 4;
            int h = kg >> 6, d = kg & 63;
            pa[i] = *(const float4*)&outh[((size_t)(b * 8 + h) * 4096 + n) * 64 + d];
            pb[i] = *(const float4*)&W[(size_t)(kb_ + i * 8) * 512 + col0 + cb * 4];
        }
    }
    for (int ci = 0; ci < 16; ci++) {
#pragma unroll
        for (int i = 0; i < 4; i++) {
            *(float4*)&As[(ra + i * 32) * AST + fa * 4] = pa[i];
            *(float4*)&Bs[(kb_ + i * 8) * BST + cb * 4] = pb[i];
        }
        __syncthreads();
        if (ci < 15) {
            int k0 = (ci + 1) * 32;
#pragma unroll
            for (int i = 0; i < 4; i++) {
                int rg = row0 + ra + i * 32;
                int b = rg >> 12, n = rg & 4095;
                int kg = k0 + fa * 4;
                int h = kg >> 6, d = kg & 63;
                pa[i] = *(const float4*)&outh[((size_t)(b * 8 + h) * 4096 + n) * 64 + d];
                pb[i] = *(const float4*)&W[(size_t)(k0 + kb_ + i * 8) * 512 + col0 + cb * 4];
            }
        }
#pragma unroll
        for (int ks = 0; ks < 4; ks++) {
            wmma::fragment<wmma::matrix_b, 16, 16, 8, wmma::precision::tf32, wmma::row_major> bf[2];
#pragma unroll
            for (int nf = 0; nf < 2; nf++) {
                wmma::load_matrix_sync(bf[nf], Bs + (ks * 8) * BST + wn * 32 + nf * 16, BST);
                CVT_FRAG(bf[nf]);
            }
#pragma unroll
            for (int mf = 0; mf < 4; mf++) {
                wmma::fragment<wmma::matrix_a, 16, 16, 8, wmma::precision::tf32, wmma::row_major> af;
                wmma::load_matrix_sync(af, As + (wm * 64 + mf * 16) * AST + ks * 8, AST);
                CVT_FRAG(af);
#pragma unroll
                for (int nf = 0; nf < 2; nf++) wmma::mma_sync(acc[mf][nf], af, bf[nf], acc[mf][nf]);
            }
        }
        __syncthreads();
    }
#pragma unroll
    for (int mf = 0; mf < 4; mf++)
#pragma unroll
        for (int nf = 0; nf < 2; nf++)
            wmma::store_matrix_sync(&out[(size_t)(row0 + wm * 64 + mf * 16) * 512 + col0 + wn * 32 + nf * 16],
                                    acc[mf][nf], 512, wmma::mem_row_major);
}

// ===== fused kernel A: outh = softmax(q@kl^T) @ tmp2 + conv(v), per 64 rows =
__global__ void k_attn1_out(const float* __restrict__ Q, const float* __restrict__ KL,
                            const float* __restrict__ T2, const float* __restrict__ V,
                            const float* __restrict__ wres, float* __restrict__ outh)
{
    extern __shared__ float smf[];
    float* qv = smf;                 // 96*72: q tile (64 x ld72), later v halo (96x64)
    float* kb = smf + 96 * 72;       // 256*72: kl (col data), later tmp2
    float* S  = kb + 256 * 72;       // 64*264: scores / later output staging (ld 72)
    __shared__ float wc[33];
    int tid = threadIdx.x, wid = tid >> 5, lane = tid & 31;
    int bh = blockIdx.y, row0 = blockIdx.x * 64;
    if (tid < 33) wc[tid] = wres[(bh & 7) * 33 + tid];

    const float* Qb = Q + ((size_t)bh * NN + row0) * 64;
    for (int i = tid; i < 64 * 16; i += 256) {
        int r = i >> 4, f = i & 15;
        *(float4*)&qv[r * 72 + f * 4] = *(const float4*)&Qb[(size_t)r * 64 + f * 4];
    }
    const float* Kb = KL + (size_t)bh * MM * 64;
    for (int i = tid; i < 256 * 16; i += 256) {
        int r = i >> 4, f = i & 15;
        *(float4*)&kb[r * 72 + f * 4] = *(const float4*)&Kb[(size_t)r * 64 + f * 4];
    }
    __syncthreads();

    // GEMM1: S(64x256) = q @ kl^T  (3xTF32; warps 2x4, warp tile 32x64)
    {
        int wm = wid >> 2, wn = wid & 3;
        wmma::fragment<wmma::accumulator, 16, 16, 8, float> a1[2][4];
#pragma unroll
        for (int mf = 0; mf < 2; mf++)
#pragma unroll
            for (int nf = 0; nf < 4; nf++) wmma::fill_fragment(a1[mf][nf], 0.f);
#pragma unroll
        for (int ks = 0; ks < 8; ks++) {
            wmma::fragment<wmma::matrix_b, 16, 16, 8, wmma::precision::tf32, wmma::col_major> bh_[4], bl_[4];
#pragma unroll
            for (int nf = 0; nf < 4; nf++) {
                wmma::fragment<wmma::matrix_b, 16, 16, 8, wmma::precision::tf32, wmma::col_major> braw;
                wmma::load_matrix_sync(braw, kb + (wn * 64 + nf * 16) * 72 + ks * 8, 72);
                split_frag(bh_[nf], bl_[nf], braw);
            }
#pragma unroll
            for (int mf = 0; mf < 2; mf++) {
                wmma::fragment<wmma::matrix_a, 16, 16, 8, wmma::precision::tf32, wmma::row_major> araw, ah, al;
                wmma::load_matrix_sync(araw, qv + (wm * 32 + mf * 16) * 72 + ks * 8, 72);
                split_frag(ah, al, araw);
#pragma unroll
                for (int nf = 0; nf < 4; nf++) {
                    wmma::mma_sync(a1[mf][nf], ah, bl_[nf], a1[mf][nf]);
                    wmma::mma_sync(a1[mf][nf], al, bh_[nf], a1[mf][nf]);
                    wmma::mma_sync(a1[mf][nf], ah, bh_[nf], a1[mf][nf]);
                }
            }
        }
#pragma unroll
        for (int mf = 0; mf < 2; mf++)
#pragma unroll
            for (int nf = 0; nf < 4; nf++)
                wmma::store_matrix_sync(S + (wm * 32 + mf * 16) * 264 + wn * 64 + nf * 16,
                                        a1[mf][nf], 264, wmma::mem_row_major);
    }
    __syncthreads();

    // softmax rows (warp wid owns rows wid*8..+7; lane group of 4 per row)
    {
        int r = wid * 8 + (lane >> 2);
        float* row = S + r * 264 + (lane & 3) * 64;
        float4 vv[16];
        float m = -FLT_MAX;
#pragma unroll
        for (int f = 0; f < 16; f++) {
            vv[f] = *(float4*)&row[f * 4];
            m = fmaxf(m, fmaxf(fmaxf(vv[f].x, vv[f].y), fmaxf(vv[f].z, vv[f].w)));
        }
        m = fmaxf(m, __shfl_xor_sync(0xffffffffu, m, 1));
        m = fmaxf(m, __shfl_xor_sync(0xffffffffu, m, 2));
        float s = 0.f;
#pragma unroll
        for (int f = 0; f < 16; f++) {
            vv[f].x = expf(vv[f].x - m); vv[f].y = expf(vv[f].y - m);
            vv[f].z = expf(vv[f].z - m); vv[f].w = expf(vv[f].w - m);
            s += vv[f].x + vv[f].y + vv[f].z + vv[f].w;
        }
        s += __shfl_xor_sync(0xffffffffu, s, 1);
        s += __shfl_xor_sync(0xffffffffu, s, 2);
        float inv = 1.f / s;
#pragma unroll
        for (int f = 0; f < 16; f++) {
            vv[f].x *= inv; vv[f].y *= inv; vv[f].z *= inv; vv[f].w *= inv;
            *(float4*)&row[f * 4] = vv[f];
        }
    }
    __syncthreads();

    // reload kb with tmp2, qv with v halo
    const float* Tb = T2 + (size_t)bh * MM * 64;
    for (int i = tid; i < 256 * 16; i += 256) {
        int r = i >> 4, f = i & 15;
        *(float4*)&kb[r * 72 + f * 4] = *(const float4*)&Tb[(size_t)r * 64 + f * 4];
    }
    for (int i = tid; i < 96 * 64; i += 256) {
        int rr = i >> 6, d = i & 63;
        int n = row0 + rr - 16;
        qv[rr * 64 + d] = (n >= 0 && n < NN) ? V[((size_t)bh * NN + n) * 64 + d] : 0.f;
    }
    __syncthreads();

    // GEMM2: O(64x64) = P(64x256) @ tmp2(256x64)  (warps 4x2, warp tile 16x32)
    int wm2 = wid >> 1, wn2 = wid & 1;
    wmma::fragment<wmma::accumulator, 16, 16, 8, float> a2[2];
#pragma unroll
    for (int nf = 0; nf < 2; nf++) wmma::fill_fragment(a2[nf], 0.f);
#pragma unroll 8
    for (int ks = 0; ks < 32; ks++) {
        wmma::fragment<wmma::matrix_a, 16, 16, 8, wmma::precision::tf32, wmma::row_major> af;
        wmma::load_matrix_sync(af, S + (wm2 * 16) * 264 + ks * 8, 264);
        CVT_FRAG(af);
#pragma unroll
        for (int nf = 0; nf < 2; nf++) {
            wmma::fragment<wmma::matrix_b, 16, 16, 8, wmma::precision::tf32, wmma::row_major> bf;
            wmma::load_matrix_sync(bf, kb + (ks * 8) * 72 + wn2 * 32 + nf * 16, 72);
            CVT_FRAG(bf);
            wmma::mma_sync(a2[nf], af, bf, a2[nf]);
        }
    }
    __syncthreads();   // all P reads done before overwriting S
#pragma unroll
    for (int nf = 0; nf < 2; nf++)
        wmma::store_matrix_sync(S + (wm2 * 16) * 72 + wn2 * 32 + nf * 16, a2[nf], 72, wmma::mem_row_major);
    __syncthreads();

    // conv residual + write
    for (int i = tid; i < 64 * 16; i += 256) {
        int r = i >> 4, c = (i & 15) * 4;
        float4 o = *(float4*)&S[r * 72 + c];
#pragma unroll 1
        for (int t = 0; t < 33; t++) {
            float w = wc[t];
            float4 vb = *(float4*)&qv[(r + t) * 64 + c];
            o.x += w * vb.x; o.y += w * vb.y; o.z += w * vb.z; o.w += w * vb.w;
        }
        *(float4*)&outh[((size_t)bh * NN + row0 + r) * 64 + c] = o;
    }
}

// ===== fused kernel B: tmp1 = softmax(ql @ k^T) @ v  (flash-style) =========
// QK logits 3xTF32; PV on tensor cores (tf32) with smem-staged rescale.
__global__ void k_flash3(const float* __restrict__ QL, const float* __restrict__ K,
                         const float* __restrict__ V, float* __restrict__ tmp1)
{
    extern __shared__ float smf[];
    float* qs = smf;                 // 64*72
    float* kt = qs + 64 * 72;        // 128*72
    float* vt = kt + 128 * 72;       // 128*72
    float* S  = vt + 128 * 72;       // 64*136
    int tid = threadIdx.x, wid = tid >> 5, lane = tid & 31;
    int bh = blockIdx.y, row0 = blockIdx.x * 64;

    const float* Qb = QL + ((size_t)bh * MM + row0) * 64;
    for (int i = tid; i < 64 * 16; i += 256) {
        int r = i >> 4, f = i & 15;
        *(float4*)&qs[r * 72 + f * 4] = *(const float4*)&Qb[(size_t)r * 64 + f * 4];
    }

    int r_loc = wid * 8 + (lane >> 2);         // this lane's row (4 lanes per row)
    int c0s = (lane & 3) * 32;                 // softmax chunk (32 cols of 128)
    int c0v = (lane & 3) * 16;                 // output chunk (16 cols of 64)
    float mrow = -1e30f, lrow = 0.f;
    float o[16];
#pragma unroll
    for (int i = 0; i < 16; i++) o[i] = 0.f;

    int wm = wid >> 2, wn = wid & 3;           // QK warp layout 2x4, warp tile 32x32
    int wm2 = wid >> 1, wn2 = wid & 1;         // PV warp layout 4x2, warp tile 16x32

    for (int nt = 0; nt < 32; nt++) {
        __syncthreads();   // prev tile's S/vt reads done
        const float* Kb = K + ((size_t)bh * NN + nt * 128) * 64;
        const float* Vb = V + ((size_t)bh * NN + nt * 128) * 64;
        for (int i = tid; i < 128 * 16; i += 256) {
            int r = i >> 4, f = i & 15;
            *(float4*)&kt[r * 72 + f * 4] = *(const float4*)&Kb[(size_t)r * 64 + f * 4];
            *(float4*)&vt[r * 72 + f * 4] = *(const float4*)&Vb[(size_t)r * 64 + f * 4];
        }
        __syncthreads();

        // S(64x128) = ql @ k^T  (3xTF32)
        wmma::fragment<wmma::accumulator, 16, 16, 8, float> a1[2][2];
#pragma unroll
        for (int mf = 0; mf < 2; mf++)
#pragma unroll
            for (int nf = 0; nf < 2; nf++) wmma::fill_fragment(a1[mf][nf], 0.f);
#pragma unroll
        for (int ks = 0; ks < 8; ks++) {
            wmma::fragment<wmma::matrix_b, 16, 16, 8, wmma::precision::tf32, wmma::col_major> bh_[2], bl_[2];
#pragma unroll
            for (int nf = 0; nf < 2; nf++) {
                wmma::fragment<wmma::matrix_b, 16, 16, 8, wmma::precision::tf32, wmma::col_major> braw;
                wmma::load_matrix_sync(braw, kt + (wn * 32 + nf * 16) * 72 + ks * 8, 72);
                split_frag(bh_[nf], bl_[nf], braw);
            }
#pragma unroll
            for (int mf = 0; mf < 2; mf++) {
                wmma::fragment<wmma::matrix_a, 16, 16, 8, wmma::precision::tf32, wmma::row_major> araw, ah, al;
                wmma::load_matrix_sync(araw, qs + (wm * 32 + mf * 16) * 72 + ks * 8, 72);
                split_frag(ah, al, araw);
#pragma unroll
                for (int nf = 0; nf < 2; nf++) {
                    wmma::mma_sync(a1[mf][nf], ah, bl_[nf], a1[mf][nf]);
                    wmma::mma_sync(a1[mf][nf], al, bh_[nf], a1[mf][nf]);
                    wmma::mma_sync(a1[mf][nf], ah, bh_[nf], a1[mf][nf]);
                }
            }
        }
#pragma unroll
        for (int mf = 0; mf < 2; mf++)
#pragma unroll
            for (int nf = 0; nf < 2; nf++)
                wmma::store_matrix_sync(S + (wm * 32 + mf * 16) * 136 + wn * 32 + nf * 16,
                                        a1[mf][nf], 136, wmma::mem_row_major);
        __syncthreads();   // softmax reads S rows written by other warps

        // online softmax update (each warp owns 8 rows; 4 lanes per row)
        float ef;
        {
            float* srow = S + r_loc * 136 + c0s;
            float4 pv[8];
            float tm = -1e30f;
#pragma unroll
            for (int f = 0; f < 8; f++) {
                pv[f] = *(float4*)&srow[f * 4];
                tm = fmaxf(tm, fmaxf(fmaxf(pv[f].x, pv[f].y), fmaxf(pv[f].z, pv[f].w)));
            }
            tm = fmaxf(tm, __shfl_xor_sync(0xffffffffu, tm, 1));
            tm = fmaxf(tm, __shfl_xor_sync(0xffffffffu, tm, 2));
            float nm = fmaxf(mrow, tm);
            ef = expf(mrow - nm);
            float ts = 0.f;
#pragma unroll
            for (int f = 0; f < 8; f++) {
                pv[f].x = expf(pv[f].x - nm); pv[f].y = expf(pv[f].y - nm);
                pv[f].z = expf(pv[f].z - nm); pv[f].w = expf(pv[f].w - nm);
                ts += pv[f].x + pv[f].y + pv[f].z + pv[f].w;
                *(float4*)&srow[f * 4] = pv[f];
            }
            ts += __shfl_xor_sync(0xffffffffu, ts, 1);
            ts += __shfl_xor_sync(0xffffffffu, ts, 2);
            lrow = lrow * ef + ts;
            mrow = nm;
        }
        __syncthreads();   // PV mma below reads all P rows

        // PV: Opart(64x64) = P(64x128) @ V(128x64) on tensor cores
        wmma::fragment<wmma::accumulator, 16, 16, 8, float> apv[2];
#pragma unroll
        for (int nf = 0; nf < 2; nf++) wmma::fill_fragment(apv[nf], 0.f);
#pragma unroll
        for (int ks = 0; ks < 16; ks++) {
            wmma::fragment<wmma::matrix_a, 16, 16, 8, wmma::precision::tf32, wmma::row_major> af;
            wmma::load_matrix_sync(af, S + (wm2 * 16) * 136 + ks * 8, 136);
            CVT_FRAG(af);
#pragma unroll
            for (int nf = 0; nf < 2; nf++) {
                wmma::fragment<wmma::matrix_b, 16, 16, 8, wmma::precision::tf32, wmma::row_major> bf;
                wmma::load_matrix_sync(bf, vt + (ks * 8) * 72 + wn2 * 32 + nf * 16, 72);
                CVT_FRAG(bf);
                wmma::mma_sync(apv[nf], af, bf, apv[nf]);
            }
        }
        __syncthreads();   // all P reads done before staging overwrites S
#pragma unroll
        for (int nf = 0; nf < 2; nf++)
            wmma::store_matrix_sync(S + (wm2 * 16) * 136 + wn2 * 32 + nf * 16,
                                    apv[nf], 136, wmma::mem_row_major);
        __syncthreads();   // staging visible to all

        // o = o*ef + Opart  (16 cols per lane)
        {
            const float* prow = S + r_loc * 136 + c0v;
#pragma unroll
            for (int cc = 0; cc < 4; cc++) {
                float4 po = *(const float4*)&prow[cc * 4];
                o[cc*4+0] = o[cc*4+0] * ef + po.x;
                o[cc*4+1] = o[cc*4+1] * ef + po.y;
                o[cc*4+2] = o[cc*4+2] * ef + po.z;
                o[cc*4+3] = o[cc*4+3] * ef + po.w;
            }
        }
    }

    float inv = 1.f / lrow;
    float* orow = tmp1 + ((size_t)bh * MM + row0 + r_loc) * 64 + c0v;
#pragma unroll
    for (int cc = 0; cc < 4; cc++) {
        float4 st = {o[cc*4] * inv, o[cc*4+1] * inv, o[cc*4+2] * inv, o[cc*4+3] * inv};
        *(float4*)&orow[cc * 4] = st;
    }
}

// ================= fp32 kernels (landmarks, sim2, pinv prep) ===============
__global__ void k_land(const float* __restrict__ q, const float* __restrict__ k,
                       float* __restrict__ ql, float* __restrict__ kl)
{
    int idx = blockIdx.x * 256 + threadIdx.x;
    int d = idx & 63;
    int m = (idx >> 6) & 255;
    int bh = idx >> 14;
    size_t base = ((size_t)bh * NN + m * LL) * DH + d;
    float sq = 0.f, sk = 0.f;
#pragma unroll
    for (int i = 0; i < LL; i++) { sq += q[base + (size_t)i * DH]; sk += k[base + (size_t)i * DH]; }
    ql[idx] = sq * (1.f / LL);
    kl[idx] = sk * (1.f / LL);
}

__global__ void k_sim_softmax(const float* __restrict__ Q, const float* __restrict__ KL,
                              float* __restrict__ Out, int nrows)
{
    extern __shared__ float smf[];
    float* ks = smf;
    float* qs = smf + 256 * 65;
    int tid = threadIdx.x;
    int bh = blockIdx.y;
    int row0 = blockIdx.x * 64;
    const float* Qb = Q + ((size_t)bh * nrows + row0) * DH;
    const float* Kb = KL + (size_t)bh * MM * DH;
    for (int i = tid; i < 256 * 64; i += 256) { int c = i >> 6, d = i & 63; ks[c * 65 + d] = Kb[i]; }
    for (int i = tid; i < 64 * 64;  i += 256) { int r = i >> 6, d = i & 63; qs[r * 65 + d] = Qb[i]; }
    __syncthreads();
    int tx = tid & 31, ty = tid >> 5;
    int c1 = tx * 4, c2 = 128 + tx * 4;
    float acc[8][8] = {};
#pragma unroll 4
    for (int d = 0; d < 64; d++) {
        float a_[8];
#pragma unroll
        for (int i = 0; i < 8; i++) a_[i] = qs[(ty * 8 + i) * 65 + d];
        float b_[8];
#pragma unroll
        for (int j = 0; j < 4; j++) { b_[j] = ks[(c1 + j) * 65 + d]; b_[4 + j] = ks[(c2 + j) * 65 + d]; }
#pragma unroll
        for (int i = 0; i < 8; i++)
#pragma unroll
            for (int j = 0; j < 8; j++) acc[i][j] += a_[i] * b_[j];
    }
#pragma unroll
    for (int i = 0; i < 8; i++) {
        float m = acc[i][0];
#pragma unroll
        for (int j = 1; j < 8; j++) m = fmaxf(m, acc[i][j]);
        for (int o = 16; o > 0; o >>= 1) m = fmaxf(m, __shfl_xor_sync(0xffffffffu, m, o));
        float s = 0.f;
#pragma unroll
        for (int j = 0; j < 8; j++) { float e = expf(acc[i][j] - m); acc[i][j] = e; s += e; }
        for (int o = 16; o > 0; o >>= 1) s += __shfl_xor_sync(0xffffffffu, s, o);
        float inv = 1.f / s;
        float* orow = Out + ((size_t)bh * nrows + row0 + ty * 8 + i) * MM;
        float4 w1 = {acc[i][0] * inv, acc[i][1] * inv, acc[i][2] * inv, acc[i][3] * inv};
        float4 w2 = {acc[i][4] * inv, acc[i][5] * inv, acc[i][6] * inv, acc[i][7] * inv};
        *(float4*)(orow + c1) = w1;
        *(float4*)(orow + c2) = w2;
    }
}

// coalesced two-pass reduction: max col-abs-sum and max row-abs-sum
__global__ void k_pinv_prep(const float* __restrict__ X, int* red)
{
    __shared__ float sred[16];
    int bh = blockIdx.x;
    int tid = threadIdx.x, wid = tid >> 5, lane = tid & 31;
    const float* Xb = X + (size_t)bh * MM * MM;

    float cs = 0.f;
    for (int i = 0; i < MM; i++) cs += fabsf(Xb[(size_t)i * MM + tid]);
    float rmax = 0.f;
    for (int row = wid; row < MM; row += 8) {
        float s = 0.f;
        const float* rp = Xb + (size_t)row * MM;
#pragma unroll
        for (int f = 0; f < 8; f++) s += fabsf(rp[lane + f * 32]);
        for (int o = 16; o > 0; o >>= 1) s += __shfl_xor_sync(0xffffffffu, s, o);
        rmax = fmaxf(rmax, s);
    }
    for (int o = 16; o > 0; o >>= 1) cs = fmaxf(cs, __shfl_xor_sync(0xffffffffu, cs, o));
    if (lane == 0) { sred[wid] = cs; sred[8 + wid] = rmax; }
    __syncthreads();
    if (wid == 0) {
        float a = (lane < 8) ? sred[lane] : 0.f;
        float b = (lane < 8) ? sred[8 + lane] : 0.f;
        for (int o = 16; o > 0; o >>= 1) {
            a = fmaxf(a, __shfl_xor_sync(0xffffffffu, a, o));
            b = fmaxf(b, __shfl_xor_sync(0xffffffffu, b, o));
        }
        if (lane == 0) {
            atomicMax(&red[0], __float_as_int(a));
            atomicMax(&red[1], __float_as_int(b));
        }
    }
}

__global__ void k_zinit(const float* __restrict__ X, float* __restrict__ Z, const int* red)
{
    float denom = __int_as_float(red[0]) * __int_as_float(red[1]) + 1e-8f;
    int idx = blockIdx.x * 256 + threadIdx.x;
    int bh = idx >> 16;
    int rem = idx & 65535;
    int i = rem >> 8, j = rem & 255;
    Z[idx] = X[((size_t)bh << 16) + j * MM + i] / denom;
}

// --------------------------- host launcher --------------------------------
extern "C" void kernel_launch(void* const* d_in, const int* in_sizes, int n_in,
                              void* d_out, int out_size)
{
    const float *x = nullptr, *wqkv = nullptr, *wout = nullptr, *wres = nullptr;
    for (int i = 0; i < n_in; i++) {
        switch (in_sizes[i]) {
            case 8388608: x = (const float*)d_in[i]; break;
            case 786432:  wqkv = (const float*)d_in[i]; break;
            case 262144:  wout = (const float*)d_in[i]; break;
            case 264:     wres = (const float*)d_in[i]; break;
            default: break;
        }
    }

    float *pq, *pk, *pv, *pql, *pkl, *pattn2;
    float *pzA, *pzB, *pxz, *pt, *pu, *ptmp1, *ptmp2, *pouth;
    int* pred;
    cudaGetSymbolAddress((void**)&pq, g_q);
    cudaGetSymbolAddress((void**)&pk, g_k);
    cudaGetSymbolAddress((void**)&pv, g_v);
    cudaGetSymbolAddress((void**)&pql, g_ql);
    cudaGetSymbolAddress((void**)&pkl, g_kl);
    cudaGetSymbolAddress((void**)&pattn2, g_attn2);
    cudaGetSymbolAddress((void**)&pzA, g_zA);
    cudaGetSymbolAddress((void**)&pzB, g_zB);
    cudaGetSymbolAddress((void**)&pxz, g_xz);
    cudaGetSymbolAddress((void**)&pt, g_t);
    cudaGetSymbolAddress((void**)&pu, g_u);
    cudaGetSymbolAddress((void**)&ptmp1, g_tmp1);
    cudaGetSymbolAddress((void**)&ptmp2, g_tmp2);
    cudaGetSymbolAddress((void**)&pouth, g_outh);
    cudaGetSymbolAddress((void**)&pred, g_red);

    size_t shmem_sim = (size_t)(256 + 64) * 65 * sizeof(float);                     // 83200
    const int SM_BIG  = (128 * AST + 32 * BST + 128 * SST) * sizeof(float);         // 107520 (qkv only)
    const int SM_G256 = (128 * AST + 32 * BST) * sizeof(float);                     // 37888
    const int SM_FIN  = (128 * AST + 32 * BST) * sizeof(float);                     // 37888
    const int SM_B64  = (128 * AST + 32 * B64ST) * sizeof(float);                   // 29696
    const int SM_AOUT = (96 * 72 + 256 * 72 + 64 * 264) * sizeof(float);            // 168960
    const int SM_FLSH = (64 * 72 + 128 * 72 + 128 * 72 + 64 * 136) * sizeof(float); // 126976
    cudaFuncSetAttribute(k_sim_softmax, cudaFuncAttributeMaxDynamicSharedMemorySize, (int)shmem_sim);
    cudaFuncSetAttribute(k_qkv_mma, cudaFuncAttributeMaxDynamicSharedMemorySize, SM_BIG);
    cudaFuncSetAttribute(k_g256_mma, cudaFuncAttributeMaxDynamicSharedMemorySize, SM_G256);
    cudaFuncSetAttribute(k_final_mma, cudaFuncAttributeMaxDynamicSharedMemorySize, SM_FIN);
    cudaFuncSetAttribute(k_b64_mma, cudaFuncAttributeMaxDynamicSharedMemorySize, SM_B64);
    cudaFuncSetAttribute(k_attn1_out, cudaFuncAttributeMaxDynamicSharedMemorySize, SM_AOUT);
    cudaFuncSetAttribute(k_flash3, cudaFuncAttributeMaxDynamicSharedMemorySize, SM_FLSH);

    // second stream + fork/join events (host objects only; capture-legal)
    cudaStream_t s1;
    cudaStreamCreate(&s1);
    cudaEvent_t evLand, evFlash;
    cudaEventCreateWithFlags(&evLand, cudaEventDisableTiming);
    cudaEventCreateWithFlags(&evFlash, cudaEventDisableTiming);

    // 1) qkv projection + head scatter (s0)
    k_qkv_mma<<<dim3(12, 128), 256, SM_BIG>>>(x, wqkv, pq, pk, pv);
    // 2) landmarks (s0)
    k_land<<<2048, 256>>>(pq, pk, pql, pkl);
    cudaEventRecord(evLand, 0);

    // fork: flash3 on s1 (needs ql, k, v only) — overlaps with the pinv chain
    cudaStreamWaitEvent(s1, evLand, 0);
    k_flash3<<<dim3(4, BH), 256, SM_FLSH, s1>>>(pql, pk, pv, ptmp1);
    cudaEventRecord(evFlash, s1);

    // 3) sim2 + softmax (s0)
    k_sim_softmax<<<dim3(4, BH), 256, shmem_sim>>>(pql, pkl, pattn2, MM);
    // 4) pinv init (s0)
    cudaMemsetAsync(pred, 0, 2 * sizeof(int));
    k_pinv_prep<<<BH, 256>>>(pattn2, pred);
    k_zinit<<<8192, 256>>>(pattn2, pzA, pred);
    // 5) 6 Newton-Schulz iterations (s0)
    float* zp = pzA;
    float* z2p = pzB;
    for (int it = 0; it < 6; it++) {
        k_g256_mma<<<dim3(2, 2, BH), 256, SM_G256>>>(pattn2, zp, pxz, 0.f, 1.f, 1.f);
        k_g256_mma<<<dim3(2, 2, BH), 256, SM_G256>>>(pxz, pxz, pt, 7.f, -1.f, 1.f);
        k_g256_mma<<<dim3(2, 2, BH), 256, SM_G256>>>(pxz, pt, pu, 15.f, -1.f, 1.f);
        k_g256_mma<<<dim3(2, 2, BH), 256, SM_G256>>>(zp, pu, z2p, 13.f, -1.f, 0.25f);
        float* sw = zp; zp = z2p; z2p = sw;
    }
    // join: b64 needs z (s0 chain) and tmp1 (s1 flash3)
    cudaStreamWaitEvent(0, evFlash, 0);
    // 7) tmp2 = z @ tmp1 (K = 256)
    k_b64_mma<<<dim3(2, BH), 256, SM_B64>>>(zp, (size_t)MM * MM, MM,
                                            ptmp1, (size_t)MM * DH, ptmp2, (size_t)MM * DH, MM);
    // 8) outh = softmax(q @ kl^T) @ tmp2 + conv(v)
    k_attn1_out<<<dim3(64, BH), 256, SM_AOUT>>>(pq, pkl, ptmp2, pv, wres, pouth);
    // 9) out = reshape(outh) @ w_out
    k_final_mma<<<dim3(4, 128), 256, SM_FIN>>>(pouth, wout, (float*)d_out);
}